// round 12
// baseline (speedup 1.0000x reference)
#include <cuda_runtime.h>
#include <cuda_bf16.h>
#include <mma.h>

using namespace nvcuda;

#define NN   50000
#define EE   800000
#define GG   256
#define HH   128
#define NHID 256
#define NOUT 128

// ---------------- scratch (static device globals; no allocations) ----------------
__device__ float g_bufA[NN * HH];
__device__ float g_bufB[NN * HH];
__device__ int   g_perm[EE];
__device__ int   g_deg[NN];
__device__ int   g_offs[NN + 1];
__device__ int   g_cursor[NN];
__device__ float g_dinv[NN];
__device__ int   g_batch[NN];
__device__ float g_pool[GG * HH];
__device__ float g_cnt[GG];
__device__ float g_hid[GG * NHID];
__device__ int   g_is64;
// bf16 split weight images, row-major [k][n] (wmma matrix_b row_major layout)
__device__ __nv_bfloat16 g_Wh[3 * 16384];
__device__ __nv_bfloat16 g_Wl[3 * 16384];

__device__ __forceinline__ float4 f4zero() { return make_float4(0.f, 0.f, 0.f, 0.f); }

// split fp32 -> (hi, lo) bf16 packed pairs
__device__ __forceinline__ void split4(float4 v, uint2& hi, uint2& lo) {
    __nv_bfloat16 bx = __float2bfloat16(v.x), by = __float2bfloat16(v.y);
    __nv_bfloat16 bz = __float2bfloat16(v.z), bw = __float2bfloat16(v.w);
    hi.x = (unsigned)__bfloat16_as_ushort(bx) | ((unsigned)__bfloat16_as_ushort(by) << 16);
    hi.y = (unsigned)__bfloat16_as_ushort(bz) | ((unsigned)__bfloat16_as_ushort(bw) << 16);
    __nv_bfloat16 lx = __float2bfloat16(v.x - __bfloat162float(bx));
    __nv_bfloat16 ly = __float2bfloat16(v.y - __bfloat162float(by));
    __nv_bfloat16 lz = __float2bfloat16(v.z - __bfloat162float(bz));
    __nv_bfloat16 lw = __float2bfloat16(v.w - __bfloat162float(bw));
    lo.x = (unsigned)__bfloat16_as_ushort(lx) | ((unsigned)__bfloat16_as_ushort(ly) << 16);
    lo.y = (unsigned)__bfloat16_as_ushort(lz) | ((unsigned)__bfloat16_as_ushort(lw) << 16);
}

// ---------------- setup: zero + dtype detect + weight bf16-split prep ------------
__global__ void k_setup(const unsigned int* __restrict__ w,
                        const float* __restrict__ W0, const float* __restrict__ Wg1,
                        const float* __restrict__ Wg2) {
    int i = blockIdx.x * blockDim.x + threadIdx.x;
    if (i < NN) g_deg[i] = 0;
    if (i < GG * HH) g_pool[i] = 0.f;
    if (i < GG) g_cnt[i] = 0.f;
    if (blockIdx.x == 0) {
        __shared__ int nz;
        if (threadIdx.x == 0) nz = 0;
        __syncthreads();
        for (int t = threadIdx.x; t < 2048; t += blockDim.x)
            if (w[2 * t + 1] != 0u) nz = 1;   // benign race
        __syncthreads();
        if (threadIdx.x == 0) g_is64 = (nz == 0) ? 1 : 0;
    }
    // weight prep: row-major [k][n] bf16 hi/lo
    int p = i - 50176;
    if (p >= 0 && p < 3 * 16384) {
        int which = p / 16384, e = p % 16384;
        const float* Ws = which == 0 ? W0 : (which == 1 ? Wg1 : Wg2);
        float v = Ws[e];
        __nv_bfloat16 h = __float2bfloat16(v);
        __nv_bfloat16 l = __float2bfloat16(v - __bfloat162float(h));
        g_Wh[which * 16384 + e] = h;
        g_Wl[which * 16384 + e] = l;
    }
}

// Degree count + batch convert + per-graph node count.
__global__ void k_count(const void* __restrict__ ei, const void* __restrict__ batch) {
    int i = blockIdx.x * blockDim.x + threadIdx.x;
    int is64 = g_is64;
    if (i < EE) {
        int d = is64 ? (int)((const long long*)ei)[EE + i] : ((const int*)ei)[EE + i];
        atomicAdd(&g_deg[d], 1);
    }
    if (i < NN) {
        int b = is64 ? (int)((const long long*)batch)[i] : ((const int*)batch)[i];
        g_batch[i] = b;
        atomicAdd(&g_cnt[b], 1.f);
    }
}

// Single-block scan + dinv.
__global__ void k_scan() {
    __shared__ int sh[1024];
    int t = threadIdx.x;
    const int C = (NN + 1023) / 1024;
    int base = t * C;
    int sum = 0;
    for (int j = 0; j < C; j++) {
        int i = base + j;
        if (i < NN) sum += g_deg[i];
    }
    sh[t] = sum;
    __syncthreads();
    for (int d = 1; d < 1024; d <<= 1) {
        int v = (t >= d) ? sh[t - d] : 0;
        __syncthreads();
        sh[t] += v;
        __syncthreads();
    }
    int run = sh[t] - sum;
    if (t == 0) g_offs[0] = 0;
    for (int j = 0; j < C; j++) {
        int i = base + j;
        if (i < NN) {
            int d = g_deg[i];
            g_cursor[i] = run;
            run += d;
            g_offs[i + 1] = run;
            g_dinv[i] = rsqrtf((float)(d + 1));
        }
    }
}

__global__ void k_fill(const void* __restrict__ ei) {
    int i = blockIdx.x * blockDim.x + threadIdx.x;
    if (i < EE) {
        int s, d;
        if (g_is64) {
            const long long* p = (const long long*)ei;
            s = (int)p[i]; d = (int)p[EE + i];
        } else {
            const int* p = (const int*)ei;
            s = p[i]; d = p[EE + i];
        }
        int slot = atomicAdd(&g_cursor[d], 1);
        g_perm[slot] = s;
    }
}

// ---------------- WMMA GEMM (+optional fused GIN gather) -------------------------
// C[M,128] = act((A[M,128] @ W[128,128]) * scale? + bias?), split-bf16 (3 products),
// fp32 accumulate. 256 threads = 8 warps; 64-row block tile; warp grid 2x4:
// warp tile = 32 rows x 32 cols (2x2 fragments). Per k-step per warp: 4 A LDSM +
// 4 B frag loads (L1-resident W) + 12 MMA -> balanced LDSM/L1 traffic.
// fused=1: A row = h[node] + sum_nbr h[nbr] (GIN aggregation).
#define AST 136     // A smem stride (bf16 elements)
#define CST 132     // epilogue smem stride (floats)

__global__ void __launch_bounds__(256)
k_wmma(const float* __restrict__ A, int widx,
       const float* __restrict__ bias, const float* __restrict__ scale,
       float* __restrict__ C, int M, int fused, int relu) {
    __shared__ __align__(16) char sm[64 * AST * 2 * 2];   // 34816 B
    __nv_bfloat16* sa_hi = (__nv_bfloat16*)sm;
    __nv_bfloat16* sa_lo = (__nv_bfloat16*)(sm + 64 * AST * 2);
    int tid = threadIdx.x, wid = tid >> 5, lane = tid & 31;
    int m0 = blockIdx.x * 64;

    // ---- A fill (split to bf16 hi/lo) ----
    if (!fused) {
        const float4* A4 = (const float4*)A;
#pragma unroll
        for (int i = 0; i < 8; i++) {
            int idx = tid + i * 256;           // 2048 float4 slots
            int r = idx >> 5, q = idx & 31;
            float4 v = (m0 + r < M) ? __ldg(&A4[(m0 + r) * 32 + q]) : f4zero();
            uint2 hi, lo;
            split4(v, hi, lo);
            *(uint2*)(sa_hi + r * AST + q * 4) = hi;
            *(uint2*)(sa_lo + r * AST + q * 4) = lo;
        }
    } else {
        const float4* h4 = (const float4*)A;
#pragma unroll 1
        for (int rr = 0; rr < 8; rr++) {
            int r = wid * 8 + rr;              // 8 warps x 8 rows = 64
            int node = m0 + r;
            float4 acc = f4zero();
            if (node < M) {
                acc = h4[node * 32 + lane];
                int s0 = g_offs[node], s1 = g_offs[node + 1];
                int j = s0;
                for (; j + 3 < s1; j += 4) {
                    int n0 = g_perm[j], n1 = g_perm[j + 1], n2 = g_perm[j + 2], n3 = g_perm[j + 3];
                    float4 u0 = h4[n0 * 32 + lane];
                    float4 u1 = h4[n1 * 32 + lane];
                    float4 u2 = h4[n2 * 32 + lane];
                    float4 u3 = h4[n3 * 32 + lane];
                    acc.x += (u0.x + u1.x) + (u2.x + u3.x);
                    acc.y += (u0.y + u1.y) + (u2.y + u3.y);
                    acc.z += (u0.z + u1.z) + (u2.z + u3.z);
                    acc.w += (u0.w + u1.w) + (u2.w + u3.w);
                }
                for (; j < s1; j++) {
                    float4 u = h4[g_perm[j] * 32 + lane];
                    acc.x += u.x; acc.y += u.y; acc.z += u.z; acc.w += u.w;
                }
            }
            uint2 hi, lo;
            split4(acc, hi, lo);
            *(uint2*)(sa_hi + r * AST + lane * 4) = hi;
            *(uint2*)(sa_lo + r * AST + lane * 4) = lo;
        }
    }
    __syncthreads();

    // ---- tensor phase: warp (wrow, wcol) owns rows wrow*32..+31, cols wcol*32..+31
    int wrow = wid >> 2;     // 0..1
    int wcol = wid & 3;      // 0..3
    wmma::fragment<wmma::accumulator, 16, 16, 16, float> facc[2][2];
#pragma unroll
    for (int r = 0; r < 2; r++)
#pragma unroll
        for (int c = 0; c < 2; c++) wmma::fill_fragment(facc[r][c], 0.f);

    const __nv_bfloat16* Bh = g_Wh + widx * 16384 + wcol * 32;
    const __nv_bfloat16* Bl = g_Wl + widx * 16384 + wcol * 32;

#pragma unroll 2
    for (int k = 0; k < 8; k++) {
        wmma::fragment<wmma::matrix_b, 16, 16, 16, __nv_bfloat16, wmma::row_major> bh[2], bl[2];
#pragma unroll
        for (int c = 0; c < 2; c++) {
            wmma::load_matrix_sync(bh[c], Bh + (k * 16) * 128 + c * 16, 128);
            wmma::load_matrix_sync(bl[c], Bl + (k * 16) * 128 + c * 16, 128);
        }
#pragma unroll
        for (int r = 0; r < 2; r++) {
            wmma::fragment<wmma::matrix_a, 16, 16, 16, __nv_bfloat16, wmma::row_major> ah, al;
            wmma::load_matrix_sync(ah, sa_hi + (wrow * 32 + r * 16) * AST + k * 16, AST);
            wmma::load_matrix_sync(al, sa_lo + (wrow * 32 + r * 16) * AST + k * 16, AST);
#pragma unroll
            for (int c = 0; c < 2; c++) {
                wmma::mma_sync(facc[r][c], ah, bh[c], facc[r][c]);
                wmma::mma_sync(facc[r][c], ah, bl[c], facc[r][c]);
                wmma::mma_sync(facc[r][c], al, bh[c], facc[r][c]);
            }
        }
    }

    // ---- epilogue via smem (reuse A area) ----
    __syncthreads();
    float* cs = (float*)sm;
#pragma unroll
    for (int r = 0; r < 2; r++)
#pragma unroll
        for (int c = 0; c < 2; c++)
            wmma::store_matrix_sync(cs + (wrow * 32 + r * 16) * CST + wcol * 32 + c * 16,
                                    facc[r][c], CST, wmma::mem_row_major);
    __syncthreads();

    const float4* b4p = (const float4*)bias;
    float4* C4 = (float4*)C;
#pragma unroll
    for (int i = 0; i < 8; i++) {
        int idx = tid + i * 256;
        int r = idx >> 5, q = idx & 31;
        int grow = m0 + r;
        if (grow < M) {
            float4 o = *(float4*)(cs + r * CST + q * 4);
            float s = scale ? scale[grow] : 1.f;
            float4 bb = f4zero();
            if (bias) bb = b4p[q];
            o.x = fmaf(o.x, s, bb.x); o.y = fmaf(o.y, s, bb.y);
            o.z = fmaf(o.z, s, bb.z); o.w = fmaf(o.w, s, bb.w);
            if (relu) {
                o.x = fmaxf(o.x, 0.f); o.y = fmaxf(o.y, 0.f);
                o.z = fmaxf(o.z, 0.f); o.w = fmaxf(o.w, 0.f);
            }
            C4[grow * 32 + q] = o;
        }
    }
}

// ---------------- GCN aggregation (standalone; h pre-scaled by dinv) -------------
__global__ void k_gcn_agg(const float* __restrict__ h, const float* __restrict__ b0,
                          float* __restrict__ out) {
    int node = blockIdx.x * 8 + (threadIdx.x >> 5);
    if (node >= NN) return;
    int lane = threadIdx.x & 31;
    const float4* h4 = (const float4*)h;

    float4 acc = h4[node * 32 + lane];
    int s0 = g_offs[node], s1 = g_offs[node + 1];
    int j = s0;
    for (; j + 3 < s1; j += 4) {
        int n0 = g_perm[j], n1 = g_perm[j + 1], n2 = g_perm[j + 2], n3 = g_perm[j + 3];
        float4 u0 = h4[n0 * 32 + lane];
        float4 u1 = h4[n1 * 32 + lane];
        float4 u2 = h4[n2 * 32 + lane];
        float4 u3 = h4[n3 * 32 + lane];
        acc.x += (u0.x + u1.x) + (u2.x + u3.x);
        acc.y += (u0.y + u1.y) + (u2.y + u3.y);
        acc.z += (u0.z + u1.z) + (u2.z + u3.z);
        acc.w += (u0.w + u1.w) + (u2.w + u3.w);
    }
    for (; j < s1; j++) {
        float4 u = h4[g_perm[j] * 32 + lane];
        acc.x += u.x; acc.y += u.y; acc.z += u.z; acc.w += u.w;
    }
    float di = g_dinv[node];
    float4 b = ((const float4*)b0)[lane];
    float4 o;
    o.x = fmaxf(fmaf(di, acc.x, b.x), 0.f);
    o.y = fmaxf(fmaf(di, acc.y, b.y), 0.f);
    o.z = fmaxf(fmaf(di, acc.z, b.z), 0.f);
    o.w = fmaxf(fmaf(di, acc.w, b.w), 0.f);
    ((float4*)out)[node * 32 + lane] = o;
}

// ---------------- mean pool: sorted batch -> run-accumulate, few atomics ---------
#define POOL_NODES 128
__global__ void k_pool(const float* __restrict__ h) {
    __shared__ int sb[POOL_NODES];
    int c = threadIdx.x;
    int n0 = blockIdx.x * POOL_NODES;
    int nend = n0 + POOL_NODES; if (nend > NN) nend = NN;
    for (int i = n0 + c; i < nend; i += 128) sb[i - n0] = g_batch[i];
    __syncthreads();

    float acc = 0.f;
    int cur = sb[0];
    for (int n = n0; n < nend; n++) {
        int g = sb[n - n0];
        if (g != cur) {
            atomicAdd(&g_pool[cur * HH + c], acc);
            acc = 0.f; cur = g;
        }
        acc += h[n * HH + c];
    }
    atomicAdd(&g_pool[cur * HH + c], acc);
}

// ---------------- head MLP ----------------
__global__ void k_head1(const float* __restrict__ Wh1, const float* __restrict__ bh1) {
    int g = blockIdx.x, c = threadIdx.x;
    float inv = 1.f / fmaxf(g_cnt[g], 1.f);
    float acc = bh1[c];
    const float* pr = &g_pool[g * HH];
#pragma unroll 8
    for (int k = 0; k < HH; k++)
        acc = fmaf(pr[k] * inv, __ldg(&Wh1[k * NHID + c]), acc);
    g_hid[g * NHID + c] = fmaxf(acc, 0.f);
}

__global__ void k_head2(const float* __restrict__ Wh2, const float* __restrict__ bh2,
                        float* __restrict__ out) {
    int g = blockIdx.x, c = threadIdx.x;
    float acc = bh2[c];
    const float* hr = &g_hid[g * NHID];
#pragma unroll 8
    for (int k = 0; k < NHID; k++)
        acc = fmaf(hr[k], __ldg(&Wh2[k * NOUT + c]), acc);
    out[g * NOUT + c] = acc;
}

// ---------------- launch ----------------
extern "C" void kernel_launch(void* const* d_in, const int* in_sizes, int n_in,
                              void* d_out, int out_size) {
    (void)in_sizes; (void)n_in; (void)out_size;
    const float* x   = (const float*)d_in[0];
    const void*  ei  = d_in[1];
    const void*  bat = d_in[2];
    const float* W0  = (const float*)d_in[3];
    const float* b0  = (const float*)d_in[4];
    const float* Wg1 = (const float*)d_in[5];
    const float* bg1 = (const float*)d_in[6];
    const float* Wg2 = (const float*)d_in[7];
    const float* bg2 = (const float*)d_in[8];
    const float* Wh1 = (const float*)d_in[9];
    const float* bh1 = (const float*)d_in[10];
    const float* Wh2 = (const float*)d_in[11];
    const float* bh2 = (const float*)d_in[12];
    float* out = (float*)d_out;

    float *bufA, *bufB, *dinv;
    cudaGetSymbolAddress((void**)&bufA, g_bufA);
    cudaGetSymbolAddress((void**)&bufB, g_bufB);
    cudaGetSymbolAddress((void**)&dinv, g_dinv);

    const int TB = 256;
    int mma_blocks = (NN + 63) / 64;     // 782
    int agg_blocks = (NN + 7) / 8;

    // 0..2: setup (+weight bf16 prep), count, scan
    k_setup<<<388, TB>>>((const unsigned int*)ei, W0, Wg1, Wg2);
    k_count<<<(EE + TB - 1) / TB, TB>>>(ei, bat);
    k_scan<<<1, 1024>>>();
    // 3: GCN transform via WMMA, row-scaled by dinv  (PROFILED LAUNCH)
    k_wmma<<<mma_blocks, 256>>>(x, 0, nullptr, dinv, bufA, NN, 0, 0);
    // 4: CSR bucket fill
    k_fill<<<(EE + TB - 1) / TB, TB>>>(ei);
    // 5: GCN aggregation (+bias+relu)
    k_gcn_agg<<<agg_blocks, 256>>>(bufA, b0, bufB);
    // 6: GIN layer 1 (fused gather + WMMA + bias + relu)
    k_wmma<<<mma_blocks, 256>>>(bufB, 1, bg1, nullptr, bufA, NN, 1, 1);
    // 7: GIN layer 2
    k_wmma<<<mma_blocks, 256>>>(bufA, 2, bg2, nullptr, bufB, NN, 1, 1);
    // 8-10: pool + head
    k_pool<<<(NN + POOL_NODES - 1) / POOL_NODES, 128>>>(bufB);
    k_head1<<<GG, NHID>>>(Wh1, bh1);
    k_head2<<<GG, NOUT>>>(Wh2, bh2, out);
}

// round 13
// speedup vs baseline: 1.5260x; 1.5260x over previous
#include <cuda_runtime.h>
#include <cuda_bf16.h>
#include <mma.h>

using namespace nvcuda;

#define NN   50000
#define EE   800000
#define GG   256
#define HH   128
#define NHID 256
#define NOUT 128

// ---------------- scratch (static device globals; no allocations) ----------------
__device__ float g_bufA[NN * HH];
__device__ float g_bufB[NN * HH];
__device__ int   g_perm[EE];
__device__ int   g_deg[NN];
__device__ int   g_offs[NN + 1];
__device__ int   g_cursor[NN];
__device__ float g_dinv[NN];
__device__ int   g_batch[NN];
__device__ float g_pool[GG * HH];
__device__ float g_cnt[GG];
__device__ float g_hid[GG * NHID];
__device__ int   g_is64;
__device__ int   g_bsum[64];
// bf16 split weight images, row-major [k][n] (wmma matrix_b row_major layout)
__device__ __nv_bfloat16 g_Wh[3 * 16384];
__device__ __nv_bfloat16 g_Wl[3 * 16384];

__device__ __forceinline__ float4 f4zero() { return make_float4(0.f, 0.f, 0.f, 0.f); }

// split fp32 -> (hi, lo) bf16 packed pairs
__device__ __forceinline__ void split4(float4 v, uint2& hi, uint2& lo) {
    __nv_bfloat16 bx = __float2bfloat16(v.x), by = __float2bfloat16(v.y);
    __nv_bfloat16 bz = __float2bfloat16(v.z), bw = __float2bfloat16(v.w);
    hi.x = (unsigned)__bfloat16_as_ushort(bx) | ((unsigned)__bfloat16_as_ushort(by) << 16);
    hi.y = (unsigned)__bfloat16_as_ushort(bz) | ((unsigned)__bfloat16_as_ushort(bw) << 16);
    __nv_bfloat16 lx = __float2bfloat16(v.x - __bfloat162float(bx));
    __nv_bfloat16 ly = __float2bfloat16(v.y - __bfloat162float(by));
    __nv_bfloat16 lz = __float2bfloat16(v.z - __bfloat162float(bz));
    __nv_bfloat16 lw = __float2bfloat16(v.w - __bfloat162float(bw));
    lo.x = (unsigned)__bfloat16_as_ushort(lx) | ((unsigned)__bfloat16_as_ushort(ly) << 16);
    lo.y = (unsigned)__bfloat16_as_ushort(lz) | ((unsigned)__bfloat16_as_ushort(lw) << 16);
}

// ---------------- setup: zero + dtype detect + weight bf16-split prep ------------
__global__ void k_setup(const unsigned int* __restrict__ w,
                        const float* __restrict__ W0, const float* __restrict__ Wg1,
                        const float* __restrict__ Wg2) {
    int i = blockIdx.x * blockDim.x + threadIdx.x;
    if (i < NN) g_deg[i] = 0;
    if (i < GG * HH) g_pool[i] = 0.f;
    if (i < GG) g_cnt[i] = 0.f;
    if (blockIdx.x == 0) {
        __shared__ int nz;
        if (threadIdx.x == 0) nz = 0;
        __syncthreads();
        for (int t = threadIdx.x; t < 2048; t += blockDim.x)
            if (w[2 * t + 1] != 0u) nz = 1;   // benign race
        __syncthreads();
        if (threadIdx.x == 0) g_is64 = (nz == 0) ? 1 : 0;
    }
    // weight prep: row-major [k][n] bf16 hi/lo
    int p = i - 50176;
    if (p >= 0 && p < 3 * 16384) {
        int which = p / 16384, e = p % 16384;
        const float* Ws = which == 0 ? W0 : (which == 1 ? Wg1 : Wg2);
        float v = Ws[e];
        __nv_bfloat16 h = __float2bfloat16(v);
        __nv_bfloat16 l = __float2bfloat16(v - __bfloat162float(h));
        g_Wh[which * 16384 + e] = h;
        g_Wl[which * 16384 + e] = l;
    }
}

// Degree count + batch convert + per-graph node count.
__global__ void k_count(const void* __restrict__ ei, const void* __restrict__ batch) {
    int i = blockIdx.x * blockDim.x + threadIdx.x;
    int is64 = g_is64;
    if (i < EE) {
        int d = is64 ? (int)((const long long*)ei)[EE + i] : ((const int*)ei)[EE + i];
        atomicAdd(&g_deg[d], 1);
    }
    if (i < NN) {
        int b = is64 ? (int)((const long long*)batch)[i] : ((const int*)batch)[i];
        g_batch[i] = b;
        atomicAdd(&g_cnt[b], 1.f);
    }
}

// ---------------- parallel 3-phase scan + dinv ------------------------------------
__global__ void k_scanA() {
    __shared__ int sh[1024];
    int b = blockIdx.x, t = threadIdx.x, i = b * 1024 + t;
    int v = (i < NN) ? g_deg[i] : 0;
    sh[t] = v;
    __syncthreads();
    for (int d = 1; d < 1024; d <<= 1) {
        int u = (t >= d) ? sh[t - d] : 0;
        __syncthreads();
        sh[t] += u;
        __syncthreads();
    }
    if (i < NN) {
        g_offs[i + 1] = sh[t];                   // local inclusive prefix
        g_dinv[i] = rsqrtf((float)(v + 1));      // +1 self loop
    }
    if (t == 1023) g_bsum[b] = sh[1023];
}

__global__ void k_scanB() {   // 1 thread: exclusive scan of 49 block sums
    int run = 0;
    for (int b = 0; b < 49; b++) { int s = g_bsum[b]; g_bsum[b] = run; run += s; }
    g_offs[0] = 0;
}

__global__ void k_scanC() {
    int b = blockIdx.x, t = threadIdx.x, i = b * 1024 + t;
    if (i < NN) {
        int off = g_offs[i + 1] + g_bsum[b];
        g_offs[i + 1] = off;
        g_cursor[i] = off - g_deg[i];
    }
}

__global__ void k_fill(const void* __restrict__ ei) {
    int i = blockIdx.x * blockDim.x + threadIdx.x;
    if (i < EE) {
        int s, d;
        if (g_is64) {
            const long long* p = (const long long*)ei;
            s = (int)p[i]; d = (int)p[EE + i];
        } else {
            const int* p = (const int*)ei;
            s = p[i]; d = p[EE + i];
        }
        int slot = atomicAdd(&g_cursor[d], 1);
        g_perm[slot] = s;
    }
}

// ---------------- WMMA GEMM (+optional fused GIN gather) -------------------------
// C[M,128] = act((A[M,128] @ W[128,128]) * scale? + bias?), split-bf16 (3 products),
// fp32 accumulate. 256 threads = 8 warps; warp tile = 64 rows x 16 cols (R10 layout:
// per k-step 2 B frag loads from L1-resident W + 8 A LDSM).
// fused=1: A row = h[node] + sum_nbr h[nbr] (GIN aggregation).
#define AST 136     // A smem stride (bf16 elements)
#define CST 132     // epilogue smem stride (floats)

__global__ void __launch_bounds__(256)
k_wmma(const float* __restrict__ A, int widx,
       const float* __restrict__ bias, const float* __restrict__ scale,
       float* __restrict__ C, int M, int fused, int relu) {
    __shared__ __align__(16) char sm[64 * AST * 2 * 2];   // 34816 B
    __nv_bfloat16* sa_hi = (__nv_bfloat16*)sm;
    __nv_bfloat16* sa_lo = (__nv_bfloat16*)(sm + 64 * AST * 2);
    int tid = threadIdx.x, wid = tid >> 5, lane = tid & 31;
    int m0 = blockIdx.x * 64;

    // ---- A fill (split to bf16 hi/lo) ----
    if (!fused) {
        const float4* A4 = (const float4*)A;
#pragma unroll
        for (int i = 0; i < 8; i++) {
            int idx = tid + i * 256;           // 2048 float4 slots
            int r = idx >> 5, q = idx & 31;
            float4 v = (m0 + r < M) ? __ldg(&A4[(m0 + r) * 32 + q]) : f4zero();
            uint2 hi, lo;
            split4(v, hi, lo);
            *(uint2*)(sa_hi + r * AST + q * 4) = hi;
            *(uint2*)(sa_lo + r * AST + q * 4) = lo;
        }
    } else {
        const float4* h4 = (const float4*)A;
#pragma unroll 1
        for (int rr = 0; rr < 8; rr++) {
            int r = wid * 8 + rr;              // 8 warps x 8 rows = 64
            int node = m0 + r;
            float4 acc = f4zero();
            if (node < M) {
                acc = h4[node * 32 + lane];
                int s0 = g_offs[node], s1 = g_offs[node + 1];
                int j = s0;
                for (; j + 3 < s1; j += 4) {
                    int n0 = g_perm[j], n1 = g_perm[j + 1], n2 = g_perm[j + 2], n3 = g_perm[j + 3];
                    float4 u0 = h4[n0 * 32 + lane];
                    float4 u1 = h4[n1 * 32 + lane];
                    float4 u2 = h4[n2 * 32 + lane];
                    float4 u3 = h4[n3 * 32 + lane];
                    acc.x += (u0.x + u1.x) + (u2.x + u3.x);
                    acc.y += (u0.y + u1.y) + (u2.y + u3.y);
                    acc.z += (u0.z + u1.z) + (u2.z + u3.z);
                    acc.w += (u0.w + u1.w) + (u2.w + u3.w);
                }
                for (; j < s1; j++) {
                    float4 u = h4[g_perm[j] * 32 + lane];
                    acc.x += u.x; acc.y += u.y; acc.z += u.z; acc.w += u.w;
                }
            }
            uint2 hi, lo;
            split4(acc, hi, lo);
            *(uint2*)(sa_hi + r * AST + lane * 4) = hi;
            *(uint2*)(sa_lo + r * AST + lane * 4) = lo;
        }
    }
    __syncthreads();

    // ---- tensor phase: warp wid owns cols wid*16..+15, all 64 rows --------------
    wmma::fragment<wmma::accumulator, 16, 16, 16, float> facc[4];
#pragma unroll
    for (int r = 0; r < 4; r++) wmma::fill_fragment(facc[r], 0.f);

    const __nv_bfloat16* Bh = g_Wh + widx * 16384 + wid * 16;
    const __nv_bfloat16* Bl = g_Wl + widx * 16384 + wid * 16;

#pragma unroll 1
    for (int k = 0; k < 8; k++) {
        wmma::fragment<wmma::matrix_b, 16, 16, 16, __nv_bfloat16, wmma::row_major> bh, bl;
        wmma::load_matrix_sync(bh, Bh + (k * 16) * 128, 128);
        wmma::load_matrix_sync(bl, Bl + (k * 16) * 128, 128);
#pragma unroll
        for (int r = 0; r < 4; r++) {
            wmma::fragment<wmma::matrix_a, 16, 16, 16, __nv_bfloat16, wmma::row_major> ah, al;
            wmma::load_matrix_sync(ah, sa_hi + (r * 16) * AST + k * 16, AST);
            wmma::load_matrix_sync(al, sa_lo + (r * 16) * AST + k * 16, AST);
            wmma::mma_sync(facc[r], ah, bh, facc[r]);
            wmma::mma_sync(facc[r], ah, bl, facc[r]);
            wmma::mma_sync(facc[r], al, bh, facc[r]);
        }
    }

    // ---- epilogue via smem (reuse A area) ----
    __syncthreads();
    float* cs = (float*)sm;
#pragma unroll
    for (int r = 0; r < 4; r++)
        wmma::store_matrix_sync(cs + (r * 16) * CST + wid * 16,
                                facc[r], CST, wmma::mem_row_major);
    __syncthreads();

    const float4* b4p = (const float4*)bias;
    float4* C4 = (float4*)C;
#pragma unroll
    for (int i = 0; i < 8; i++) {
        int idx = tid + i * 256;
        int r = idx >> 5, q = idx & 31;
        int grow = m0 + r;
        if (grow < M) {
            float4 o = *(float4*)(cs + r * CST + q * 4);
            float s = scale ? scale[grow] : 1.f;
            float4 bb = f4zero();
            if (bias) bb = b4p[q];
            o.x = fmaf(o.x, s, bb.x); o.y = fmaf(o.y, s, bb.y);
            o.z = fmaf(o.z, s, bb.z); o.w = fmaf(o.w, s, bb.w);
            if (relu) {
                o.x = fmaxf(o.x, 0.f); o.y = fmaxf(o.y, 0.f);
                o.z = fmaxf(o.z, 0.f); o.w = fmaxf(o.w, 0.f);
            }
            C4[grow * 32 + q] = o;
        }
    }
}

// ---------------- GCN aggregation (h unscaled; per-edge dinv) --------------------
// out = relu(b0 + dinv_i*(dinv_i*h[i] + sum_s dinv[s]*h[s]))
__global__ void k_gcn_agg(const float* __restrict__ h, const float* __restrict__ b0,
                          float* __restrict__ out) {
    int node = blockIdx.x * 8 + (threadIdx.x >> 5);
    if (node >= NN) return;
    int lane = threadIdx.x & 31;
    const float4* h4 = (const float4*)h;

    float di = g_dinv[node];
    float4 hs = h4[node * 32 + lane];
    float4 acc = make_float4(di * hs.x, di * hs.y, di * hs.z, di * hs.w);
    int s0 = g_offs[node], s1 = g_offs[node + 1];
    int j = s0;
    for (; j + 3 < s1; j += 4) {
        int n0 = g_perm[j], n1 = g_perm[j + 1], n2 = g_perm[j + 2], n3 = g_perm[j + 3];
        float c0 = g_dinv[n0], c1 = g_dinv[n1], c2 = g_dinv[n2], c3 = g_dinv[n3];
        float4 u0 = h4[n0 * 32 + lane];
        float4 u1 = h4[n1 * 32 + lane];
        float4 u2 = h4[n2 * 32 + lane];
        float4 u3 = h4[n3 * 32 + lane];
        acc.x = fmaf(c0, u0.x, fmaf(c1, u1.x, fmaf(c2, u2.x, fmaf(c3, u3.x, acc.x))));
        acc.y = fmaf(c0, u0.y, fmaf(c1, u1.y, fmaf(c2, u2.y, fmaf(c3, u3.y, acc.y))));
        acc.z = fmaf(c0, u0.z, fmaf(c1, u1.z, fmaf(c2, u2.z, fmaf(c3, u3.z, acc.z))));
        acc.w = fmaf(c0, u0.w, fmaf(c1, u1.w, fmaf(c2, u2.w, fmaf(c3, u3.w, acc.w))));
    }
    for (; j < s1; j++) {
        int n0 = g_perm[j];
        float c0 = g_dinv[n0];
        float4 u = h4[n0 * 32 + lane];
        acc.x = fmaf(c0, u.x, acc.x); acc.y = fmaf(c0, u.y, acc.y);
        acc.z = fmaf(c0, u.z, acc.z); acc.w = fmaf(c0, u.w, acc.w);
    }
    float4 b = ((const float4*)b0)[lane];
    float4 o;
    o.x = fmaxf(fmaf(di, acc.x, b.x), 0.f);
    o.y = fmaxf(fmaf(di, acc.y, b.y), 0.f);
    o.z = fmaxf(fmaf(di, acc.z, b.z), 0.f);
    o.w = fmaxf(fmaf(di, acc.w, b.w), 0.f);
    ((float4*)out)[node * 32 + lane] = o;
}

// ---------------- mean pool: sorted batch -> run-accumulate, few atomics ---------
#define POOL_NODES 128
__global__ void k_pool(const float* __restrict__ h) {
    __shared__ int sb[POOL_NODES];
    int c = threadIdx.x;
    int n0 = blockIdx.x * POOL_NODES;
    int nend = n0 + POOL_NODES; if (nend > NN) nend = NN;
    for (int i = n0 + c; i < nend; i += 128) sb[i - n0] = g_batch[i];
    __syncthreads();

    float acc = 0.f;
    int cur = sb[0];
    for (int n = n0; n < nend; n++) {
        int g = sb[n - n0];
        if (g != cur) {
            atomicAdd(&g_pool[cur * HH + c], acc);
            acc = 0.f; cur = g;
        }
        acc += h[n * HH + c];
    }
    atomicAdd(&g_pool[cur * HH + c], acc);
}

// ---------------- head MLP ----------------
__global__ void k_head1(const float* __restrict__ Wh1, const float* __restrict__ bh1) {
    int g = blockIdx.x, c = threadIdx.x;
    float inv = 1.f / fmaxf(g_cnt[g], 1.f);
    float acc = bh1[c];
    const float* pr = &g_pool[g * HH];
#pragma unroll 8
    for (int k = 0; k < HH; k++)
        acc = fmaf(pr[k] * inv, __ldg(&Wh1[k * NHID + c]), acc);
    g_hid[g * NHID + c] = fmaxf(acc, 0.f);
}

__global__ void k_head2(const float* __restrict__ Wh2, const float* __restrict__ bh2,
                        float* __restrict__ out) {
    int g = blockIdx.x, c = threadIdx.x;
    float acc = bh2[c];
    const float* hr = &g_hid[g * NHID];
#pragma unroll 8
    for (int k = 0; k < NHID; k++)
        acc = fmaf(hr[k], __ldg(&Wh2[k * NOUT + c]), acc);
    out[g * NOUT + c] = acc;
}

// ---------------- launch ----------------
extern "C" void kernel_launch(void* const* d_in, const int* in_sizes, int n_in,
                              void* d_out, int out_size) {
    (void)in_sizes; (void)n_in; (void)out_size;
    const float* x   = (const float*)d_in[0];
    const void*  ei  = d_in[1];
    const void*  bat = d_in[2];
    const float* W0  = (const float*)d_in[3];
    const float* b0  = (const float*)d_in[4];
    const float* Wg1 = (const float*)d_in[5];
    const float* bg1 = (const float*)d_in[6];
    const float* Wg2 = (const float*)d_in[7];
    const float* bg2 = (const float*)d_in[8];
    const float* Wh1 = (const float*)d_in[9];
    const float* bh1 = (const float*)d_in[10];
    const float* Wh2 = (const float*)d_in[11];
    const float* bh2 = (const float*)d_in[12];
    float* out = (float*)d_out;

    float *bufA, *bufB;
    cudaGetSymbolAddress((void**)&bufA, g_bufA);
    cudaGetSymbolAddress((void**)&bufB, g_bufB);

    // side stream + events, created once (handles persist; no device allocations)
    static cudaStream_t s2 = nullptr;
    static cudaEvent_t evA = nullptr, evB = nullptr;
    if (!s2) {
        cudaStreamCreateWithFlags(&s2, cudaStreamNonBlocking);
        cudaEventCreateWithFlags(&evA, cudaEventDisableTiming);
        cudaEventCreateWithFlags(&evB, cudaEventDisableTiming);
    }

    const int TB = 256;
    int mma_blocks = (NN + 63) / 64;     // 782
    int agg_blocks = (NN + 7) / 8;

    // setup (zero + detect + weight images)
    k_setup<<<388, TB>>>((const unsigned int*)ei, W0, Wg1, Wg2);

    // fork: GEMM1 (x @ W0, unscaled) on s2, concurrent with the CSR build chain
    cudaEventRecord(evA, 0);
    cudaStreamWaitEvent(s2, evA, 0);
    k_wmma<<<mma_blocks, 256, 0, s2>>>(x, 0, nullptr, nullptr, bufA, NN, 0, 0);
    cudaEventRecord(evB, s2);

    // main: CSR build
    k_count<<<(EE + TB - 1) / TB, TB>>>(ei, bat);
    k_scanA<<<49, 1024>>>();
    k_scanB<<<1, 1>>>();
    k_scanC<<<49, 1024>>>();
    k_fill<<<(EE + TB - 1) / TB, TB>>>(ei);

    // join: gcn_agg needs both bufA (GEMM1) and the CSR
    cudaStreamWaitEvent(0, evB, 0);
    k_gcn_agg<<<agg_blocks, 256>>>(bufA, b0, bufB);
    // GIN layer 1 (fused gather + WMMA + bias + relu)
    k_wmma<<<mma_blocks, 256>>>(bufB, 1, bg1, nullptr, bufA, NN, 1, 1);
    // GIN layer 2
    k_wmma<<<mma_blocks, 256>>>(bufA, 2, bg2, nullptr, bufB, NN, 1, 1);
    // pool + head
    k_pool<<<(NN + POOL_NODES - 1) / POOL_NODES, 128>>>(bufB);
    k_head1<<<GG, NHID>>>(Wh1, bh1);
    k_head2<<<GG, NOUT>>>(Wh2, bh2, out);
}

// round 14
// speedup vs baseline: 1.5799x; 1.0353x over previous
#include <cuda_runtime.h>
#include <cuda_bf16.h>
#include <cuda_fp16.h>
#include <mma.h>

using namespace nvcuda;

#define NN   50000
#define EE   800000
#define GG   256
#define HH   128
#define NHID 256
#define NOUT 128

// ---------------- scratch (static device globals; no allocations) ----------------
__device__ __half g_h0[NN * HH];     // GEMM1 output (x @ W0)
__device__ __half g_h1[NN * HH];     // GCN layer output
__device__ __half g_h2[NN * HH];     // GIN1 output
__device__ float g_bufB[NN * HH];    // GIN2 output (fp32 for pool)
__device__ int   g_perm[EE];
__device__ int   g_deg[NN];
__device__ int   g_offs[NN + 1];
__device__ int   g_cursor[NN];
__device__ float g_dinv[NN];
__device__ int   g_batch[NN];
__device__ float g_pool[GG * HH];
__device__ float g_cnt[GG];
__device__ float g_hid[GG * NHID];
__device__ int   g_is64;
__device__ int   g_bsum[64];
// bf16 split weight images, row-major [k][n] (wmma matrix_b row_major layout)
__device__ __nv_bfloat16 g_Wh[3 * 16384];
__device__ __nv_bfloat16 g_Wl[3 * 16384];

__device__ __forceinline__ float4 f4zero() { return make_float4(0.f, 0.f, 0.f, 0.f); }

// 4 halves (uint2) <-> float4
__device__ __forceinline__ float4 h2f4(uint2 v) {
    __half2 a = *(__half2*)&v.x, b = *(__half2*)&v.y;
    float2 fa = __half22float2(a), fb = __half22float2(b);
    return make_float4(fa.x, fa.y, fb.x, fb.y);
}
__device__ __forceinline__ uint2 f42h(float4 o) {
    __half2 a = __float22half2_rn(make_float2(o.x, o.y));
    __half2 b = __float22half2_rn(make_float2(o.z, o.w));
    uint2 r; r.x = *(unsigned*)&a; r.y = *(unsigned*)&b; return r;
}

// split fp32 -> (hi, lo) bf16 packed pairs
__device__ __forceinline__ void split4(float4 v, uint2& hi, uint2& lo) {
    __nv_bfloat16 bx = __float2bfloat16(v.x), by = __float2bfloat16(v.y);
    __nv_bfloat16 bz = __float2bfloat16(v.z), bw = __float2bfloat16(v.w);
    hi.x = (unsigned)__bfloat16_as_ushort(bx) | ((unsigned)__bfloat16_as_ushort(by) << 16);
    hi.y = (unsigned)__bfloat16_as_ushort(bz) | ((unsigned)__bfloat16_as_ushort(bw) << 16);
    __nv_bfloat16 lx = __float2bfloat16(v.x - __bfloat162float(bx));
    __nv_bfloat16 ly = __float2bfloat16(v.y - __bfloat162float(by));
    __nv_bfloat16 lz = __float2bfloat16(v.z - __bfloat162float(bz));
    __nv_bfloat16 lw = __float2bfloat16(v.w - __bfloat162float(bw));
    lo.x = (unsigned)__bfloat16_as_ushort(lx) | ((unsigned)__bfloat16_as_ushort(ly) << 16);
    lo.y = (unsigned)__bfloat16_as_ushort(lz) | ((unsigned)__bfloat16_as_ushort(lw) << 16);
}

// ---------------- setup: zero + dtype detect + weight bf16-split prep ------------
__global__ void k_setup(const unsigned int* __restrict__ w,
                        const float* __restrict__ W0, const float* __restrict__ Wg1,
                        const float* __restrict__ Wg2) {
    int i = blockIdx.x * blockDim.x + threadIdx.x;
    if (i < NN) g_deg[i] = 0;
    if (i < GG * HH) g_pool[i] = 0.f;
    if (i < GG) g_cnt[i] = 0.f;
    if (blockIdx.x == 0) {
        __shared__ int nz;
        if (threadIdx.x == 0) nz = 0;
        __syncthreads();
        for (int t = threadIdx.x; t < 2048; t += blockDim.x)
            if (w[2 * t + 1] != 0u) nz = 1;   // benign race
        __syncthreads();
        if (threadIdx.x == 0) g_is64 = (nz == 0) ? 1 : 0;
    }
    // weight prep: row-major [k][n] bf16 hi/lo
    int p = i - 50176;
    if (p >= 0 && p < 3 * 16384) {
        int which = p / 16384, e = p % 16384;
        const float* Ws = which == 0 ? W0 : (which == 1 ? Wg1 : Wg2);
        float v = Ws[e];
        __nv_bfloat16 h = __float2bfloat16(v);
        __nv_bfloat16 l = __float2bfloat16(v - __bfloat162float(h));
        g_Wh[which * 16384 + e] = h;
        g_Wl[which * 16384 + e] = l;
    }
}

// Degree count + batch convert + per-graph node count.
__global__ void k_count(const void* __restrict__ ei, const void* __restrict__ batch) {
    int i = blockIdx.x * blockDim.x + threadIdx.x;
    int is64 = g_is64;
    if (i < EE) {
        int d = is64 ? (int)((const long long*)ei)[EE + i] : ((const int*)ei)[EE + i];
        atomicAdd(&g_deg[d], 1);
    }
    if (i < NN) {
        int b = is64 ? (int)((const long long*)batch)[i] : ((const int*)batch)[i];
        g_batch[i] = b;
        atomicAdd(&g_cnt[b], 1.f);
    }
}

// ---------------- parallel 3-phase scan + dinv ------------------------------------
__global__ void k_scanA() {
    __shared__ int sh[1024];
    int b = blockIdx.x, t = threadIdx.x, i = b * 1024 + t;
    int v = (i < NN) ? g_deg[i] : 0;
    sh[t] = v;
    __syncthreads();
    for (int d = 1; d < 1024; d <<= 1) {
        int u = (t >= d) ? sh[t - d] : 0;
        __syncthreads();
        sh[t] += u;
        __syncthreads();
    }
    if (i < NN) {
        g_offs[i + 1] = sh[t];                   // local inclusive prefix
        g_dinv[i] = rsqrtf((float)(v + 1));      // +1 self loop
    }
    if (t == 1023) g_bsum[b] = sh[1023];
}

__global__ void k_scanB() {   // 1 thread: exclusive scan of 49 block sums
    int run = 0;
    for (int b = 0; b < 49; b++) { int s = g_bsum[b]; g_bsum[b] = run; run += s; }
    g_offs[0] = 0;
}

__global__ void k_scanC() {
    int b = blockIdx.x, t = threadIdx.x, i = b * 1024 + t;
    if (i < NN) {
        int off = g_offs[i + 1] + g_bsum[b];
        g_offs[i + 1] = off;
        g_cursor[i] = off - g_deg[i];
    }
}

__global__ void k_fill(const void* __restrict__ ei) {
    int i = blockIdx.x * blockDim.x + threadIdx.x;
    if (i < EE) {
        int s, d;
        if (g_is64) {
            const long long* p = (const long long*)ei;
            s = (int)p[i]; d = (int)p[EE + i];
        } else {
            const int* p = (const int*)ei;
            s = p[i]; d = p[EE + i];
        }
        int slot = atomicAdd(&g_cursor[d], 1);
        g_perm[slot] = s;
    }
}

// ---------------- WMMA GEMM (+optional fused GIN gather) -------------------------
// C[M,128] = act((A[M,128] @ W[128,128]) + bias?), split-bf16 (3 products),
// fp32 accumulate. 256 threads = 8 warps; warp tile = 64 rows x 16 cols.
// fused=0: A fp32. fused=1: A half; row = h[node] + sum_nbr h[nbr] (GIN agg).
// out_half: write C as half plane (uint2/lane) else float4.
#define AST 136     // A smem stride (bf16 elements)
#define CST 132     // epilogue smem stride (floats)

__global__ void __launch_bounds__(256)
k_wmma(const void* __restrict__ Ain, int widx,
       const float* __restrict__ bias,
       void* __restrict__ Cout, int M, int fused, int relu, int out_half) {
    __shared__ __align__(16) char sm[64 * AST * 2 * 2];   // 34816 B
    __nv_bfloat16* sa_hi = (__nv_bfloat16*)sm;
    __nv_bfloat16* sa_lo = (__nv_bfloat16*)(sm + 64 * AST * 2);
    int tid = threadIdx.x, wid = tid >> 5, lane = tid & 31;
    int m0 = blockIdx.x * 64;

    // ---- A fill (split to bf16 hi/lo) ----
    if (!fused) {
        const float4* A4 = (const float4*)Ain;
#pragma unroll
        for (int i = 0; i < 8; i++) {
            int idx = tid + i * 256;           // 2048 float4 slots
            int r = idx >> 5, q = idx & 31;
            float4 v = (m0 + r < M) ? __ldg(&A4[(m0 + r) * 32 + q]) : f4zero();
            uint2 hi, lo;
            split4(v, hi, lo);
            *(uint2*)(sa_hi + r * AST + q * 4) = hi;
            *(uint2*)(sa_lo + r * AST + q * 4) = lo;
        }
    } else {
        const uint2* hh = (const uint2*)Ain;   // 4 halves per lane
#pragma unroll 1
        for (int rr = 0; rr < 8; rr++) {
            int r = wid * 8 + rr;              // 8 warps x 8 rows = 64
            int node = m0 + r;
            float4 acc = f4zero();
            if (node < M) {
                acc = h2f4(hh[node * 32 + lane]);
                int s0 = g_offs[node], s1 = g_offs[node + 1];
                int j = s0;
                for (; j + 3 < s1; j += 4) {
                    int n0 = g_perm[j], n1 = g_perm[j + 1], n2 = g_perm[j + 2], n3 = g_perm[j + 3];
                    float4 u0 = h2f4(hh[n0 * 32 + lane]);
                    float4 u1 = h2f4(hh[n1 * 32 + lane]);
                    float4 u2 = h2f4(hh[n2 * 32 + lane]);
                    float4 u3 = h2f4(hh[n3 * 32 + lane]);
                    acc.x += (u0.x + u1.x) + (u2.x + u3.x);
                    acc.y += (u0.y + u1.y) + (u2.y + u3.y);
                    acc.z += (u0.z + u1.z) + (u2.z + u3.z);
                    acc.w += (u0.w + u1.w) + (u2.w + u3.w);
                }
                for (; j < s1; j++) {
                    float4 u = h2f4(hh[g_perm[j] * 32 + lane]);
                    acc.x += u.x; acc.y += u.y; acc.z += u.z; acc.w += u.w;
                }
            }
            uint2 hi, lo;
            split4(acc, hi, lo);
            *(uint2*)(sa_hi + r * AST + lane * 4) = hi;
            *(uint2*)(sa_lo + r * AST + lane * 4) = lo;
        }
    }
    __syncthreads();

    // ---- tensor phase: warp wid owns cols wid*16..+15, all 64 rows --------------
    wmma::fragment<wmma::accumulator, 16, 16, 16, float> facc[4];
#pragma unroll
    for (int r = 0; r < 4; r++) wmma::fill_fragment(facc[r], 0.f);

    const __nv_bfloat16* Bh = g_Wh + widx * 16384 + wid * 16;
    const __nv_bfloat16* Bl = g_Wl + widx * 16384 + wid * 16;

#pragma unroll 1
    for (int k = 0; k < 8; k++) {
        wmma::fragment<wmma::matrix_b, 16, 16, 16, __nv_bfloat16, wmma::row_major> bh, bl;
        wmma::load_matrix_sync(bh, Bh + (k * 16) * 128, 128);
        wmma::load_matrix_sync(bl, Bl + (k * 16) * 128, 128);
#pragma unroll
        for (int r = 0; r < 4; r++) {
            wmma::fragment<wmma::matrix_a, 16, 16, 16, __nv_bfloat16, wmma::row_major> ah, al;
            wmma::load_matrix_sync(ah, sa_hi + (r * 16) * AST + k * 16, AST);
            wmma::load_matrix_sync(al, sa_lo + (r * 16) * AST + k * 16, AST);
            wmma::mma_sync(facc[r], ah, bh, facc[r]);
            wmma::mma_sync(facc[r], ah, bl, facc[r]);
            wmma::mma_sync(facc[r], al, bh, facc[r]);
        }
    }

    // ---- epilogue via smem (reuse A area) ----
    __syncthreads();
    float* cs = (float*)sm;
#pragma unroll
    for (int r = 0; r < 4; r++)
        wmma::store_matrix_sync(cs + (r * 16) * CST + wid * 16,
                                facc[r], CST, wmma::mem_row_major);
    __syncthreads();

    const float4* b4p = (const float4*)bias;
#pragma unroll
    for (int i = 0; i < 8; i++) {
        int idx = tid + i * 256;
        int r = idx >> 5, q = idx & 31;
        int grow = m0 + r;
        if (grow < M) {
            float4 o = *(float4*)(cs + r * CST + q * 4);
            if (bias) {
                float4 bb = b4p[q];
                o.x += bb.x; o.y += bb.y; o.z += bb.z; o.w += bb.w;
            }
            if (relu) {
                o.x = fmaxf(o.x, 0.f); o.y = fmaxf(o.y, 0.f);
                o.z = fmaxf(o.z, 0.f); o.w = fmaxf(o.w, 0.f);
            }
            if (out_half)
                ((uint2*)Cout)[grow * 32 + q] = f42h(o);
            else
                ((float4*)Cout)[grow * 32 + q] = o;
        }
    }
}

// ---------------- GCN aggregation (half in, half out; per-edge dinv) -------------
// out = relu(b0 + dinv_i*(dinv_i*h[i] + sum_s dinv[s]*h[s]))
__global__ void k_gcn_agg(const __half* __restrict__ h, const float* __restrict__ b0,
                          __half* __restrict__ out) {
    int node = blockIdx.x * 8 + (threadIdx.x >> 5);
    if (node >= NN) return;
    int lane = threadIdx.x & 31;
    const uint2* h2 = (const uint2*)h;

    float di = g_dinv[node];
    float4 hs = h2f4(h2[node * 32 + lane]);
    float4 acc = make_float4(di * hs.x, di * hs.y, di * hs.z, di * hs.w);
    int s0 = g_offs[node], s1 = g_offs[node + 1];
    int j = s0;
    for (; j + 3 < s1; j += 4) {
        int n0 = g_perm[j], n1 = g_perm[j + 1], n2 = g_perm[j + 2], n3 = g_perm[j + 3];
        float c0 = g_dinv[n0], c1 = g_dinv[n1], c2 = g_dinv[n2], c3 = g_dinv[n3];
        float4 u0 = h2f4(h2[n0 * 32 + lane]);
        float4 u1 = h2f4(h2[n1 * 32 + lane]);
        float4 u2 = h2f4(h2[n2 * 32 + lane]);
        float4 u3 = h2f4(h2[n3 * 32 + lane]);
        acc.x = fmaf(c0, u0.x, fmaf(c1, u1.x, fmaf(c2, u2.x, fmaf(c3, u3.x, acc.x))));
        acc.y = fmaf(c0, u0.y, fmaf(c1, u1.y, fmaf(c2, u2.y, fmaf(c3, u3.y, acc.y))));
        acc.z = fmaf(c0, u0.z, fmaf(c1, u1.z, fmaf(c2, u2.z, fmaf(c3, u3.z, acc.z))));
        acc.w = fmaf(c0, u0.w, fmaf(c1, u1.w, fmaf(c2, u2.w, fmaf(c3, u3.w, acc.w))));
    }
    for (; j < s1; j++) {
        int n0 = g_perm[j];
        float c0 = g_dinv[n0];
        float4 u = h2f4(h2[n0 * 32 + lane]);
        acc.x = fmaf(c0, u.x, acc.x); acc.y = fmaf(c0, u.y, acc.y);
        acc.z = fmaf(c0, u.z, acc.z); acc.w = fmaf(c0, u.w, acc.w);
    }
    float4 b = ((const float4*)b0)[lane];
    float4 o;
    o.x = fmaxf(fmaf(di, acc.x, b.x), 0.f);
    o.y = fmaxf(fmaf(di, acc.y, b.y), 0.f);
    o.z = fmaxf(fmaf(di, acc.z, b.z), 0.f);
    o.w = fmaxf(fmaf(di, acc.w, b.w), 0.f);
    ((uint2*)out)[node * 32 + lane] = f42h(o);
}

// ---------------- mean pool: sorted batch -> run-accumulate, few atomics ---------
#define POOL_NODES 128
__global__ void k_pool(const float* __restrict__ h) {
    __shared__ int sb[POOL_NODES];
    int c = threadIdx.x;
    int n0 = blockIdx.x * POOL_NODES;
    int nend = n0 + POOL_NODES; if (nend > NN) nend = NN;
    for (int i = n0 + c; i < nend; i += 128) sb[i - n0] = g_batch[i];
    __syncthreads();

    float acc = 0.f;
    int cur = sb[0];
    for (int n = n0; n < nend; n++) {
        int g = sb[n - n0];
        if (g != cur) {
            atomicAdd(&g_pool[cur * HH + c], acc);
            acc = 0.f; cur = g;
        }
        acc += h[n * HH + c];
    }
    atomicAdd(&g_pool[cur * HH + c], acc);
}

// ---------------- head MLP ----------------
__global__ void k_head1(const float* __restrict__ Wh1, const float* __restrict__ bh1) {
    int g = blockIdx.x, c = threadIdx.x;
    float inv = 1.f / fmaxf(g_cnt[g], 1.f);
    float acc = bh1[c];
    const float* pr = &g_pool[g * HH];
#pragma unroll 8
    for (int k = 0; k < HH; k++)
        acc = fmaf(pr[k] * inv, __ldg(&Wh1[k * NHID + c]), acc);
    g_hid[g * NHID + c] = fmaxf(acc, 0.f);
}

__global__ void k_head2(const float* __restrict__ Wh2, const float* __restrict__ bh2,
                        float* __restrict__ out) {
    int g = blockIdx.x, c = threadIdx.x;
    float acc = bh2[c];
    const float* hr = &g_hid[g * NHID];
#pragma unroll 8
    for (int k = 0; k < NHID; k++)
        acc = fmaf(hr[k], __ldg(&Wh2[k * NOUT + c]), acc);
    out[g * NOUT + c] = acc;
}

// ---------------- launch ----------------
extern "C" void kernel_launch(void* const* d_in, const int* in_sizes, int n_in,
                              void* d_out, int out_size) {
    (void)in_sizes; (void)n_in; (void)out_size;
    const float* x   = (const float*)d_in[0];
    const void*  ei  = d_in[1];
    const void*  bat = d_in[2];
    const float* W0  = (const float*)d_in[3];
    const float* b0  = (const float*)d_in[4];
    const float* Wg1 = (const float*)d_in[5];
    const float* bg1 = (const float*)d_in[6];
    const float* Wg2 = (const float*)d_in[7];
    const float* bg2 = (const float*)d_in[8];
    const float* Wh1 = (const float*)d_in[9];
    const float* bh1 = (const float*)d_in[10];
    const float* Wh2 = (const float*)d_in[11];
    const float* bh2 = (const float*)d_in[12];
    float* out = (float*)d_out;

    __half *h0, *h1, *h2;
    float *bufB;
    cudaGetSymbolAddress((void**)&h0, g_h0);
    cudaGetSymbolAddress((void**)&h1, g_h1);
    cudaGetSymbolAddress((void**)&h2, g_h2);
    cudaGetSymbolAddress((void**)&bufB, g_bufB);

    // side stream + events, created once (handles persist; no device allocations)
    static cudaStream_t s2 = nullptr;
    static cudaEvent_t evA = nullptr, evB = nullptr;
    if (!s2) {
        cudaStreamCreateWithFlags(&s2, cudaStreamNonBlocking);
        cudaEventCreateWithFlags(&evA, cudaEventDisableTiming);
        cudaEventCreateWithFlags(&evB, cudaEventDisableTiming);
    }

    const int TB = 256;
    int mma_blocks = (NN + 63) / 64;     // 782
    int agg_blocks = (NN + 7) / 8;

    // setup (zero + detect + weight images)
    k_setup<<<388, TB>>>((const unsigned int*)ei, W0, Wg1, Wg2);

    // fork: GEMM1 (x @ W0 -> h0 fp16) on s2, concurrent with the CSR build chain
    cudaEventRecord(evA, 0);
    cudaStreamWaitEvent(s2, evA, 0);
    k_wmma<<<mma_blocks, 256, 0, s2>>>(x, 0, nullptr, h0, NN, 0, 0, 1);
    cudaEventRecord(evB, s2);

    // main: CSR build
    k_count<<<(EE + TB - 1) / TB, TB>>>(ei, bat);
    k_scanA<<<49, 1024>>>();
    k_scanB<<<1, 1>>>();
    k_scanC<<<49, 1024>>>();
    k_fill<<<(EE + TB - 1) / TB, TB>>>(ei);

    // join: gcn_agg needs both h0 (GEMM1) and the CSR
    cudaStreamWaitEvent(0, evB, 0);
    k_gcn_agg<<<agg_blocks, 256>>>(h0, b0, h1);
    // GIN layer 1 (fused half gather + WMMA + bias + relu -> h2 fp16)
    k_wmma<<<mma_blocks, 256>>>(h1, 1, bg1, h2, NN, 1, 1, 1);
    // GIN layer 2 (fused half gather + WMMA + bias + relu -> fp32 for pool)
    k_wmma<<<mma_blocks, 256>>>(h2, 2, bg2, bufB, NN, 1, 1, 0);
    // pool + head
    k_pool<<<(NN + POOL_NODES - 1) / POOL_NODES, 128>>>(bufB);
    k_head1<<<GG, NHID>>>(Wh1, bh1);
    k_head2<<<GG, NOUT>>>(Wh2, bh2, out);
}

// round 15
// speedup vs baseline: 1.7410x; 1.1019x over previous
#include <cuda_runtime.h>
#include <cuda_bf16.h>
#include <cuda_fp16.h>
#include <mma.h>

using namespace nvcuda;

#define NN   50000
#define EE   800000
#define GG   256
#define HH   128
#define NHID 256
#define NOUT 128

// ---------------- scratch (static device globals; no allocations) ----------------
__device__ __half g_h0[NN * HH];     // GEMM1 output (x @ W0)
__device__ __half g_h1[NN * HH];     // GCN layer output
__device__ __half g_h2[NN * HH];     // GIN1 output
__device__ int   g_perm[EE];
__device__ int   g_deg[NN];
__device__ int   g_offs[NN + 1];
__device__ int   g_cursor[NN];
__device__ float g_dinv[NN];
__device__ int   g_batch[NN];
__device__ float g_pool[GG * HH];
__device__ float g_cnt[GG];
__device__ float g_hid[GG * NHID];
__device__ int   g_is64;
__device__ int   g_bsum[64];
// bf16 split weight images, row-major [k][n] (wmma matrix_b row_major layout)
__device__ __nv_bfloat16 g_Wh[3 * 16384];
__device__ __nv_bfloat16 g_Wl[3 * 16384];

__device__ __forceinline__ float4 f4zero() { return make_float4(0.f, 0.f, 0.f, 0.f); }

// 4 halves (uint2) <-> float4
__device__ __forceinline__ float4 h2f4(uint2 v) {
    __half2 a = *(__half2*)&v.x, b = *(__half2*)&v.y;
    float2 fa = __half22float2(a), fb = __half22float2(b);
    return make_float4(fa.x, fa.y, fb.x, fb.y);
}
__device__ __forceinline__ uint2 f42h(float4 o) {
    __half2 a = __float22half2_rn(make_float2(o.x, o.y));
    __half2 b = __float22half2_rn(make_float2(o.z, o.w));
    uint2 r; r.x = *(unsigned*)&a; r.y = *(unsigned*)&b; return r;
}

// split fp32 -> (hi, lo) bf16 packed pairs
__device__ __forceinline__ void split4(float4 v, uint2& hi, uint2& lo) {
    __nv_bfloat16 bx = __float2bfloat16(v.x), by = __float2bfloat16(v.y);
    __nv_bfloat16 bz = __float2bfloat16(v.z), bw = __float2bfloat16(v.w);
    hi.x = (unsigned)__bfloat16_as_ushort(bx) | ((unsigned)__bfloat16_as_ushort(by) << 16);
    hi.y = (unsigned)__bfloat16_as_ushort(bz) | ((unsigned)__bfloat16_as_ushort(bw) << 16);
    __nv_bfloat16 lx = __float2bfloat16(v.x - __bfloat162float(bx));
    __nv_bfloat16 ly = __float2bfloat16(v.y - __bfloat162float(by));
    __nv_bfloat16 lz = __float2bfloat16(v.z - __bfloat162float(bz));
    __nv_bfloat16 lw = __float2bfloat16(v.w - __bfloat162float(bw));
    lo.x = (unsigned)__bfloat16_as_ushort(lx) | ((unsigned)__bfloat16_as_ushort(ly) << 16);
    lo.y = (unsigned)__bfloat16_as_ushort(lz) | ((unsigned)__bfloat16_as_ushort(lw) << 16);
}

// ---------------- setup: zero + dtype detect + weight bf16-split prep ------------
__global__ void k_setup(const unsigned int* __restrict__ w,
                        const float* __restrict__ W0, const float* __restrict__ Wg1,
                        const float* __restrict__ Wg2) {
    int i = blockIdx.x * blockDim.x + threadIdx.x;
    if (i < NN) g_deg[i] = 0;
    if (i < GG * HH) g_pool[i] = 0.f;
    if (i < GG) g_cnt[i] = 0.f;
    if (blockIdx.x == 0) {
        __shared__ int nz;
        if (threadIdx.x == 0) nz = 0;
        __syncthreads();
        for (int t = threadIdx.x; t < 2048; t += blockDim.x)
            if (w[2 * t + 1] != 0u) nz = 1;   // benign race
        __syncthreads();
        if (threadIdx.x == 0) g_is64 = (nz == 0) ? 1 : 0;
    }
    // weight prep: row-major [k][n] bf16 hi/lo
    int p = i - 50176;
    if (p >= 0 && p < 3 * 16384) {
        int which = p / 16384, e = p % 16384;
        const float* Ws = which == 0 ? W0 : (which == 1 ? Wg1 : Wg2);
        float v = Ws[e];
        __nv_bfloat16 h = __float2bfloat16(v);
        __nv_bfloat16 l = __float2bfloat16(v - __bfloat162float(h));
        g_Wh[which * 16384 + e] = h;
        g_Wl[which * 16384 + e] = l;
    }
}

// Degree count + batch convert + per-graph node count.
__global__ void k_count(const void* __restrict__ ei, const void* __restrict__ batch) {
    int i = blockIdx.x * blockDim.x + threadIdx.x;
    int is64 = g_is64;
    if (i < EE) {
        int d = is64 ? (int)((const long long*)ei)[EE + i] : ((const int*)ei)[EE + i];
        atomicAdd(&g_deg[d], 1);
    }
    if (i < NN) {
        int b = is64 ? (int)((const long long*)batch)[i] : ((const int*)batch)[i];
        g_batch[i] = b;
        atomicAdd(&g_cnt[b], 1.f);
    }
}

// ---------------- parallel 3-phase scan + dinv ------------------------------------
__global__ void k_scanA() {
    __shared__ int sh[1024];
    int b = blockIdx.x, t = threadIdx.x, i = b * 1024 + t;
    int v = (i < NN) ? g_deg[i] : 0;
    sh[t] = v;
    __syncthreads();
    for (int d = 1; d < 1024; d <<= 1) {
        int u = (t >= d) ? sh[t - d] : 0;
        __syncthreads();
        sh[t] += u;
        __syncthreads();
    }
    if (i < NN) {
        g_offs[i + 1] = sh[t];                   // local inclusive prefix
        g_dinv[i] = rsqrtf((float)(v + 1));      // +1 self loop
    }
    if (t == 1023) g_bsum[b] = sh[1023];
}

__global__ void k_scanB() {   // 1 thread: exclusive scan of 49 block sums
    int run = 0;
    for (int b = 0; b < 49; b++) { int s = g_bsum[b]; g_bsum[b] = run; run += s; }
    g_offs[0] = 0;
}

__global__ void k_scanC() {
    int b = blockIdx.x, t = threadIdx.x, i = b * 1024 + t;
    if (i < NN) {
        int off = g_offs[i + 1] + g_bsum[b];
        g_offs[i + 1] = off;
        g_cursor[i] = off - g_deg[i];
    }
}

__global__ void k_fill(const void* __restrict__ ei) {
    int i = blockIdx.x * blockDim.x + threadIdx.x;
    if (i < EE) {
        int s, d;
        if (g_is64) {
            const long long* p = (const long long*)ei;
            s = (int)p[i]; d = (int)p[EE + i];
        } else {
            const int* p = (const int*)ei;
            s = p[i]; d = p[EE + i];
        }
        int slot = atomicAdd(&g_cursor[d], 1);
        g_perm[slot] = s;
    }
}

// sum 8 gathered half rows into acc (8 loads in flight)
#define GATHER8(hh, base_j)                                                     \
    do {                                                                        \
        int nA = g_perm[(base_j)],     nB = g_perm[(base_j) + 1];               \
        int nC = g_perm[(base_j) + 2], nD = g_perm[(base_j) + 3];               \
        int nE = g_perm[(base_j) + 4], nF = g_perm[(base_j) + 5];               \
        int nG = g_perm[(base_j) + 6], nH = g_perm[(base_j) + 7];               \
        uint2 rA = hh[nA * 32 + lane], rB = hh[nB * 32 + lane];                 \
        uint2 rC = hh[nC * 32 + lane], rD = hh[nD * 32 + lane];                 \
        uint2 rE = hh[nE * 32 + lane], rF = hh[nF * 32 + lane];                 \
        uint2 rG = hh[nG * 32 + lane], rH = hh[nH * 32 + lane];                 \
        float4 uA = h2f4(rA), uB = h2f4(rB), uC = h2f4(rC), uD = h2f4(rD);      \
        float4 uE = h2f4(rE), uF = h2f4(rF), uG = h2f4(rG), uH = h2f4(rH);      \
        acc.x += ((uA.x + uB.x) + (uC.x + uD.x)) + ((uE.x + uF.x) + (uG.x + uH.x)); \
        acc.y += ((uA.y + uB.y) + (uC.y + uD.y)) + ((uE.y + uF.y) + (uG.y + uH.y)); \
        acc.z += ((uA.z + uB.z) + (uC.z + uD.z)) + ((uE.z + uF.z) + (uG.z + uH.z)); \
        acc.w += ((uA.w + uB.w) + (uC.w + uD.w)) + ((uE.w + uF.w) + (uG.w + uH.w)); \
    } while (0)

// ---------------- WMMA GEMM (+optional fused GIN gather, +optional fused pool) ---
// C[M,128] = act((A[M,128] @ W[128,128]) + bias?), split-bf16 (3 products),
// fp32 accumulate. 256 threads = 8 warps; warp tile = 64 rows x 16 cols.
// fused=0: A fp32. fused=1: A half; row = h[node] + sum_nbr h[nbr] (GIN agg).
// mode 0: write C fp32; mode 1: write C half; mode 2: no C write, accumulate
//         rows into g_pool[batch[node]] (bias+relu applied inside).
#define AST 136     // A smem stride (bf16 elements)
#define CST 132     // epilogue smem stride (floats)

__global__ void __launch_bounds__(256)
k_wmma(const void* __restrict__ Ain, int widx,
       const float* __restrict__ bias,
       void* __restrict__ Cout, int M, int fused, int relu, int mode) {
    __shared__ __align__(16) char sm[64 * AST * 2 * 2];   // 34816 B
    __shared__ int sbat[64];
    __nv_bfloat16* sa_hi = (__nv_bfloat16*)sm;
    __nv_bfloat16* sa_lo = (__nv_bfloat16*)(sm + 64 * AST * 2);
    int tid = threadIdx.x, wid = tid >> 5, lane = tid & 31;
    int m0 = blockIdx.x * 64;

    // ---- A fill (split to bf16 hi/lo) ----
    if (!fused) {
        const float4* A4 = (const float4*)Ain;
#pragma unroll
        for (int i = 0; i < 8; i++) {
            int idx = tid + i * 256;           // 2048 float4 slots
            int r = idx >> 5, q = idx & 31;
            float4 v = (m0 + r < M) ? __ldg(&A4[(m0 + r) * 32 + q]) : f4zero();
            uint2 hi, lo;
            split4(v, hi, lo);
            *(uint2*)(sa_hi + r * AST + q * 4) = hi;
            *(uint2*)(sa_lo + r * AST + q * 4) = lo;
        }
    } else {
        const uint2* hh = (const uint2*)Ain;   // 4 halves per lane
#pragma unroll 1
        for (int rr = 0; rr < 8; rr++) {
            int r = wid * 8 + rr;              // 8 warps x 8 rows = 64
            int node = m0 + r;
            float4 acc = f4zero();
            if (node < M) {
                acc = h2f4(hh[node * 32 + lane]);
                int s0 = g_offs[node], s1 = g_offs[node + 1];
                int j = s0;
                for (; j + 7 < s1; j += 8) GATHER8(hh, j);
                for (; j < s1; j++) {
                    float4 u = h2f4(hh[g_perm[j] * 32 + lane]);
                    acc.x += u.x; acc.y += u.y; acc.z += u.z; acc.w += u.w;
                }
            }
            uint2 hi, lo;
            split4(acc, hi, lo);
            *(uint2*)(sa_hi + r * AST + lane * 4) = hi;
            *(uint2*)(sa_lo + r * AST + lane * 4) = lo;
        }
    }
    if (mode == 2 && tid < 64)
        sbat[tid] = (m0 + tid < M) ? g_batch[m0 + tid] : -1;
    __syncthreads();

    // ---- tensor phase: warp wid owns cols wid*16..+15, all 64 rows --------------
    wmma::fragment<wmma::accumulator, 16, 16, 16, float> facc[4];
#pragma unroll
    for (int r = 0; r < 4; r++) wmma::fill_fragment(facc[r], 0.f);

    const __nv_bfloat16* Bh = g_Wh + widx * 16384 + wid * 16;
    const __nv_bfloat16* Bl = g_Wl + widx * 16384 + wid * 16;

#pragma unroll 1
    for (int k = 0; k < 8; k++) {
        wmma::fragment<wmma::matrix_b, 16, 16, 16, __nv_bfloat16, wmma::row_major> bh, bl;
        wmma::load_matrix_sync(bh, Bh + (k * 16) * 128, 128);
        wmma::load_matrix_sync(bl, Bl + (k * 16) * 128, 128);
#pragma unroll
        for (int r = 0; r < 4; r++) {
            wmma::fragment<wmma::matrix_a, 16, 16, 16, __nv_bfloat16, wmma::row_major> ah, al;
            wmma::load_matrix_sync(ah, sa_hi + (r * 16) * AST + k * 16, AST);
            wmma::load_matrix_sync(al, sa_lo + (r * 16) * AST + k * 16, AST);
            wmma::mma_sync(facc[r], ah, bh, facc[r]);
            wmma::mma_sync(facc[r], ah, bl, facc[r]);
            wmma::mma_sync(facc[r], al, bh, facc[r]);
        }
    }

    // ---- epilogue via smem (reuse A area) ----
    __syncthreads();
    float* cs = (float*)sm;
#pragma unroll
    for (int r = 0; r < 4; r++)
        wmma::store_matrix_sync(cs + (r * 16) * CST + wid * 16,
                                facc[r], CST, wmma::mem_row_major);
    __syncthreads();

    if (mode == 2) {
        // fused mean-pool accumulate: 2 threads per column, 32 sorted rows each.
        int c = tid & 127;
        int r0 = (tid >> 7) * 32, r1 = r0 + 32;
        float b = bias ? bias[c] : 0.f;
        float acc = 0.f;
        int cur = sbat[r0];
        for (int r = r0; r < r1; r++) {
            int g = sbat[r];
            if (g < 0) break;
            if (g != cur) {
                atomicAdd(&g_pool[cur * HH + c], acc);
                acc = 0.f; cur = g;
            }
            acc += fmaxf(cs[r * CST + c] + b, 0.f);
        }
        if (cur >= 0 && acc != 0.f) atomicAdd(&g_pool[cur * HH + c], acc);
        return;
    }

    const float4* b4p = (const float4*)bias;
#pragma unroll
    for (int i = 0; i < 8; i++) {
        int idx = tid + i * 256;
        int r = idx >> 5, q = idx & 31;
        int grow = m0 + r;
        if (grow < M) {
            float4 o = *(float4*)(cs + r * CST + q * 4);
            if (bias) {
                float4 bb = b4p[q];
                o.x += bb.x; o.y += bb.y; o.z += bb.z; o.w += bb.w;
            }
            if (relu) {
                o.x = fmaxf(o.x, 0.f); o.y = fmaxf(o.y, 0.f);
                o.z = fmaxf(o.z, 0.f); o.w = fmaxf(o.w, 0.f);
            }
            if (mode == 1)
                ((uint2*)Cout)[grow * 32 + q] = f42h(o);
            else
                ((float4*)Cout)[grow * 32 + q] = o;
        }
    }
}

// ---------------- GCN aggregation (half in, half out; per-edge dinv) -------------
// out = relu(b0 + dinv_i*(dinv_i*h[i] + sum_s dinv[s]*h[s]))
__global__ void k_gcn_agg(const __half* __restrict__ h, const float* __restrict__ b0,
                          __half* __restrict__ out) {
    int node = blockIdx.x * 8 + (threadIdx.x >> 5);
    if (node >= NN) return;
    int lane = threadIdx.x & 31;
    const uint2* hh = (const uint2*)h;

    float di = g_dinv[node];
    float4 hs = h2f4(hh[node * 32 + lane]);
    float4 acc = make_float4(di * hs.x, di * hs.y, di * hs.z, di * hs.w);
    int s0 = g_offs[node], s1 = g_offs[node + 1];
    int j = s0;
    for (; j + 7 < s1; j += 8) {
        int nA = g_perm[j],     nB = g_perm[j + 1], nC = g_perm[j + 2], nD = g_perm[j + 3];
        int nE = g_perm[j + 4], nF = g_perm[j + 5], nG = g_perm[j + 6], nH = g_perm[j + 7];
        float cA = g_dinv[nA], cB = g_dinv[nB], cC = g_dinv[nC], cD = g_dinv[nD];
        float cE = g_dinv[nE], cF = g_dinv[nF], cG = g_dinv[nG], cH = g_dinv[nH];
        float4 uA = h2f4(hh[nA * 32 + lane]), uB = h2f4(hh[nB * 32 + lane]);
        float4 uC = h2f4(hh[nC * 32 + lane]), uD = h2f4(hh[nD * 32 + lane]);
        float4 uE = h2f4(hh[nE * 32 + lane]), uF = h2f4(hh[nF * 32 + lane]);
        float4 uG = h2f4(hh[nG * 32 + lane]), uH = h2f4(hh[nH * 32 + lane]);
        acc.x = fmaf(cA, uA.x, fmaf(cB, uB.x, fmaf(cC, uC.x, fmaf(cD, uD.x,
                fmaf(cE, uE.x, fmaf(cF, uF.x, fmaf(cG, uG.x, fmaf(cH, uH.x, acc.x))))))));
        acc.y = fmaf(cA, uA.y, fmaf(cB, uB.y, fmaf(cC, uC.y, fmaf(cD, uD.y,
                fmaf(cE, uE.y, fmaf(cF, uF.y, fmaf(cG, uG.y, fmaf(cH, uH.y, acc.y))))))));
        acc.z = fmaf(cA, uA.z, fmaf(cB, uB.z, fmaf(cC, uC.z, fmaf(cD, uD.z,
                fmaf(cE, uE.z, fmaf(cF, uF.z, fmaf(cG, uG.z, fmaf(cH, uH.z, acc.z))))))));
        acc.w = fmaf(cA, uA.w, fmaf(cB, uB.w, fmaf(cC, uC.w, fmaf(cD, uD.w,
                fmaf(cE, uE.w, fmaf(cF, uF.w, fmaf(cG, uG.w, fmaf(cH, uH.w, acc.w))))))));
    }
    for (; j < s1; j++) {
        int n0 = g_perm[j];
        float c0 = g_dinv[n0];
        float4 u = h2f4(hh[n0 * 32 + lane]);
        acc.x = fmaf(c0, u.x, acc.x); acc.y = fmaf(c0, u.y, acc.y);
        acc.z = fmaf(c0, u.z, acc.z); acc.w = fmaf(c0, u.w, acc.w);
    }
    float4 b = ((const float4*)b0)[lane];
    float4 o;
    o.x = fmaxf(fmaf(di, acc.x, b.x), 0.f);
    o.y = fmaxf(fmaf(di, acc.y, b.y), 0.f);
    o.z = fmaxf(fmaf(di, acc.z, b.z), 0.f);
    o.w = fmaxf(fmaf(di, acc.w, b.w), 0.f);
    ((uint2*)out)[node * 32 + lane] = f42h(o);
}

// ---------------- head MLP ----------------
__global__ void k_head1(const float* __restrict__ Wh1, const float* __restrict__ bh1) {
    int g = blockIdx.x, c = threadIdx.x;
    float inv = 1.f / fmaxf(g_cnt[g], 1.f);
    float acc = bh1[c];
    const float* pr = &g_pool[g * HH];
#pragma unroll 8
    for (int k = 0; k < HH; k++)
        acc = fmaf(pr[k] * inv, __ldg(&Wh1[k * NHID + c]), acc);
    g_hid[g * NHID + c] = fmaxf(acc, 0.f);
}

__global__ void k_head2(const float* __restrict__ Wh2, const float* __restrict__ bh2,
                        float* __restrict__ out) {
    int g = blockIdx.x, c = threadIdx.x;
    float acc = bh2[c];
    const float* hr = &g_hid[g * NHID];
#pragma unroll 8
    for (int k = 0; k < NHID; k++)
        acc = fmaf(hr[k], __ldg(&Wh2[k * NOUT + c]), acc);
    out[g * NOUT + c] = acc;
}

// ---------------- launch ----------------
extern "C" void kernel_launch(void* const* d_in, const int* in_sizes, int n_in,
                              void* d_out, int out_size) {
    (void)in_sizes; (void)n_in; (void)out_size;
    const float* x   = (const float*)d_in[0];
    const void*  ei  = d_in[1];
    const void*  bat = d_in[2];
    const float* W0  = (const float*)d_in[3];
    const float* b0  = (const float*)d_in[4];
    const float* Wg1 = (const float*)d_in[5];
    const float* bg1 = (const float*)d_in[6];
    const float* Wg2 = (const float*)d_in[7];
    const float* bg2 = (const float*)d_in[8];
    const float* Wh1 = (const float*)d_in[9];
    const float* bh1 = (const float*)d_in[10];
    const float* Wh2 = (const float*)d_in[11];
    const float* bh2 = (const float*)d_in[12];
    float* out = (float*)d_out;

    __half *h0, *h1, *h2;
    cudaGetSymbolAddress((void**)&h0, g_h0);
    cudaGetSymbolAddress((void**)&h1, g_h1);
    cudaGetSymbolAddress((void**)&h2, g_h2);

    // side stream + events, created once (handles persist; no device allocations)
    static cudaStream_t s2 = nullptr;
    static cudaEvent_t evA = nullptr, evB = nullptr;
    if (!s2) {
        cudaStreamCreateWithFlags(&s2, cudaStreamNonBlocking);
        cudaEventCreateWithFlags(&evA, cudaEventDisableTiming);
        cudaEventCreateWithFlags(&evB, cudaEventDisableTiming);
    }

    const int TB = 256;
    int mma_blocks = (NN + 63) / 64;     // 782
    int agg_blocks = (NN + 7) / 8;

    // setup (zero + detect + weight images)
    k_setup<<<388, TB>>>((const unsigned int*)ei, W0, Wg1, Wg2);

    // fork: GEMM1 (x @ W0 -> h0 fp16) on s2, concurrent with the CSR build chain
    cudaEventRecord(evA, 0);
    cudaStreamWaitEvent(s2, evA, 0);
    k_wmma<<<mma_blocks, 256, 0, s2>>>(x, 0, nullptr, h0, NN, 0, 0, 1);
    cudaEventRecord(evB, s2);

    // main: CSR build
    k_count<<<(EE + TB - 1) / TB, TB>>>(ei, bat);
    k_scanA<<<49, 1024>>>();
    k_scanB<<<1, 1>>>();
    k_scanC<<<49, 1024>>>();
    k_fill<<<(EE + TB - 1) / TB, TB>>>(ei);

    // join: gcn_agg needs both h0 (GEMM1) and the CSR
    cudaStreamWaitEvent(0, evB, 0);
    k_gcn_agg<<<agg_blocks, 256>>>(h0, b0, h1);
    // GIN layer 1 (fused half gather + WMMA + bias + relu -> h2 fp16)
    k_wmma<<<mma_blocks, 256>>>(h1, 1, bg1, h2, NN, 1, 1, 1);
    // GIN layer 2 (fused half gather + WMMA; epilogue pools directly, no C write)
    k_wmma<<<mma_blocks, 256>>>(h2, 2, bg2, nullptr, NN, 1, 1, 2);
    // heads
    k_head1<<<GG, NHID>>>(Wh1, bh1);
    k_head2<<<GG, NOUT>>>(Wh2, bh2, out);
}

// round 16
// speedup vs baseline: 1.7895x; 1.0279x over previous
#include <cuda_runtime.h>
#include <cuda_bf16.h>
#include <cuda_fp16.h>
#include <mma.h>

using namespace nvcuda;

#define NN   50000
#define EE   800000
#define GG   256
#define HH   128
#define NHID 256
#define NOUT 128

// ---------------- scratch (static device globals; no allocations) ----------------
__device__ __half g_h0[NN * HH];     // GEMM1 output (x @ W0)
__device__ __half g_h1[NN * HH];     // GCN layer output
__device__ __half g_h2[NN * HH];     // GIN1 output
__device__ int   g_perm[EE];
__device__ int   g_deg[NN];
__device__ int   g_offs[NN + 1];
__device__ int   g_cursor[NN];
__device__ float g_dinv[NN];
__device__ int   g_batch[NN];
__device__ float g_pool[GG * HH];
__device__ float g_cnt[GG];
__device__ int   g_is64;
__device__ int   g_bsum[64];
// bf16 split weight images, row-major [k][n] (wmma matrix_b row_major layout)
__device__ __nv_bfloat16 g_Wh[3 * 16384];
__device__ __nv_bfloat16 g_Wl[3 * 16384];

__device__ __forceinline__ float4 f4zero() { return make_float4(0.f, 0.f, 0.f, 0.f); }

// 4 halves (uint2) <-> float4
__device__ __forceinline__ float4 h2f4(uint2 v) {
    __half2 a = *(__half2*)&v.x, b = *(__half2*)&v.y;
    float2 fa = __half22float2(a), fb = __half22float2(b);
    return make_float4(fa.x, fa.y, fb.x, fb.y);
}
__device__ __forceinline__ uint2 f42h(float4 o) {
    __half2 a = __float22half2_rn(make_float2(o.x, o.y));
    __half2 b = __float22half2_rn(make_float2(o.z, o.w));
    uint2 r; r.x = *(unsigned*)&a; r.y = *(unsigned*)&b; return r;
}

// split fp32 -> (hi, lo) bf16 packed pairs
__device__ __forceinline__ void split4(float4 v, uint2& hi, uint2& lo) {
    __nv_bfloat16 bx = __float2bfloat16(v.x), by = __float2bfloat16(v.y);
    __nv_bfloat16 bz = __float2bfloat16(v.z), bw = __float2bfloat16(v.w);
    hi.x = (unsigned)__bfloat16_as_ushort(bx) | ((unsigned)__bfloat16_as_ushort(by) << 16);
    hi.y = (unsigned)__bfloat16_as_ushort(bz) | ((unsigned)__bfloat16_as_ushort(bw) << 16);
    __nv_bfloat16 lx = __float2bfloat16(v.x - __bfloat162float(bx));
    __nv_bfloat16 ly = __float2bfloat16(v.y - __bfloat162float(by));
    __nv_bfloat16 lz = __float2bfloat16(v.z - __bfloat162float(bz));
    __nv_bfloat16 lw = __float2bfloat16(v.w - __bfloat162float(bw));
    lo.x = (unsigned)__bfloat16_as_ushort(lx) | ((unsigned)__bfloat16_as_ushort(ly) << 16);
    lo.y = (unsigned)__bfloat16_as_ushort(lz) | ((unsigned)__bfloat16_as_ushort(lw) << 16);
}

// ---------------- setup: zero + dtype detect + weight bf16-split prep ------------
__global__ void k_setup(const unsigned int* __restrict__ w,
                        const float* __restrict__ W0, const float* __restrict__ Wg1,
                        const float* __restrict__ Wg2) {
    int i = blockIdx.x * blockDim.x + threadIdx.x;
    if (i < NN) g_deg[i] = 0;
    if (i < GG * HH) g_pool[i] = 0.f;
    if (i < GG) g_cnt[i] = 0.f;
    if (blockIdx.x == 0) {
        __shared__ int nz;
        if (threadIdx.x == 0) nz = 0;
        __syncthreads();
        for (int t = threadIdx.x; t < 2048; t += blockDim.x)
            if (w[2 * t + 1] != 0u) nz = 1;   // benign race
        __syncthreads();
        if (threadIdx.x == 0) g_is64 = (nz == 0) ? 1 : 0;
    }
    // weight prep: row-major [k][n] bf16 hi/lo
    int p = i - 50176;
    if (p >= 0 && p < 3 * 16384) {
        int which = p / 16384, e = p % 16384;
        const float* Ws = which == 0 ? W0 : (which == 1 ? Wg1 : Wg2);
        float v = Ws[e];
        __nv_bfloat16 h = __float2bfloat16(v);
        __nv_bfloat16 l = __float2bfloat16(v - __bfloat162float(h));
        g_Wh[which * 16384 + e] = h;
        g_Wl[which * 16384 + e] = l;
    }
}

// Degree count + batch convert + per-graph node count.
__global__ void k_count(const void* __restrict__ ei, const void* __restrict__ batch) {
    int i = blockIdx.x * blockDim.x + threadIdx.x;
    int is64 = g_is64;
    if (i < EE) {
        int d = is64 ? (int)((const long long*)ei)[EE + i] : ((const int*)ei)[EE + i];
        atomicAdd(&g_deg[d], 1);
    }
    if (i < NN) {
        int b = is64 ? (int)((const long long*)batch)[i] : ((const int*)batch)[i];
        g_batch[i] = b;
        atomicAdd(&g_cnt[b], 1.f);
    }
}

// ---------------- parallel 3-phase scan + dinv ------------------------------------
__global__ void k_scanA() {
    __shared__ int sh[1024];
    int b = blockIdx.x, t = threadIdx.x, i = b * 1024 + t;
    int v = (i < NN) ? g_deg[i] : 0;
    sh[t] = v;
    __syncthreads();
    for (int d = 1; d < 1024; d <<= 1) {
        int u = (t >= d) ? sh[t - d] : 0;
        __syncthreads();
        sh[t] += u;
        __syncthreads();
    }
    if (i < NN) {
        g_offs[i + 1] = sh[t];                   // local inclusive prefix
        g_dinv[i] = rsqrtf((float)(v + 1));      // +1 self loop
    }
    if (t == 1023) g_bsum[b] = sh[1023];
}

__global__ void k_scanB() {   // 1 thread: exclusive scan of 49 block sums
    int run = 0;
    for (int b = 0; b < 49; b++) { int s = g_bsum[b]; g_bsum[b] = run; run += s; }
    g_offs[0] = 0;
}

__global__ void k_scanC() {
    int b = blockIdx.x, t = threadIdx.x, i = b * 1024 + t;
    if (i < NN) {
        int off = g_offs[i + 1] + g_bsum[b];
        g_offs[i + 1] = off;
        g_cursor[i] = off - g_deg[i];
    }
}

__global__ void k_fill(const void* __restrict__ ei) {
    int i = blockIdx.x * blockDim.x + threadIdx.x;
    if (i < EE) {
        int s, d;
        if (g_is64) {
            const long long* p = (const long long*)ei;
            s = (int)p[i]; d = (int)p[EE + i];
        } else {
            const int* p = (const int*)ei;
            s = p[i]; d = p[EE + i];
        }
        int slot = atomicAdd(&g_cursor[d], 1);
        g_perm[slot] = s;
    }
}

// sum 16 gathered half rows into acc (16 loads in flight)
#define GATHER16(hh, base_j)                                                    \
    do {                                                                        \
        int ix[16];                                                             \
        _Pragma("unroll")                                                       \
        for (int t = 0; t < 16; t++) ix[t] = g_perm[(base_j) + t];              \
        uint2 rr[16];                                                           \
        _Pragma("unroll")                                                       \
        for (int t = 0; t < 16; t++) rr[t] = hh[ix[t] * 32 + lane];             \
        _Pragma("unroll")                                                       \
        for (int t = 0; t < 16; t += 4) {                                       \
            float4 uA = h2f4(rr[t]), uB = h2f4(rr[t + 1]);                      \
            float4 uC = h2f4(rr[t + 2]), uD = h2f4(rr[t + 3]);                  \
            acc.x += (uA.x + uB.x) + (uC.x + uD.x);                             \
            acc.y += (uA.y + uB.y) + (uC.y + uD.y);                             \
            acc.z += (uA.z + uB.z) + (uC.z + uD.z);                             \
            acc.w += (uA.w + uB.w) + (uC.w + uD.w);                             \
        }                                                                       \
    } while (0)

// ---------------- WMMA GEMM (+optional fused GIN gather, +optional fused pool) ---
// C[M,128] = act((A[M,128] @ W[128,128]) + bias?), split-bf16 (3 products),
// fp32 accumulate. 256 threads = 8 warps; warp tile = 64 rows x 16 cols.
// fused=0: A fp32. fused=1: A half; row = h[node] + sum_nbr h[nbr] (GIN agg).
// mode 0: write C fp32; mode 1: write C half; mode 2: no C write, accumulate
//         rows into g_pool[batch[node]] (bias+relu applied inside).
#define AST 136     // A smem stride (bf16 elements)
#define CST 132     // epilogue smem stride (floats)

__global__ void __launch_bounds__(256)
k_wmma(const void* __restrict__ Ain, int widx,
       const float* __restrict__ bias,
       void* __restrict__ Cout, int M, int fused, int relu, int mode) {
    __shared__ __align__(16) char sm[64 * AST * 2 * 2];   // 34816 B
    __shared__ int sbat[64];
    __nv_bfloat16* sa_hi = (__nv_bfloat16*)sm;
    __nv_bfloat16* sa_lo = (__nv_bfloat16*)(sm + 64 * AST * 2);
    int tid = threadIdx.x, wid = tid >> 5, lane = tid & 31;
    int m0 = blockIdx.x * 64;

    // ---- A fill (split to bf16 hi/lo) ----
    if (!fused) {
        const float4* A4 = (const float4*)Ain;
#pragma unroll
        for (int i = 0; i < 8; i++) {
            int idx = tid + i * 256;           // 2048 float4 slots
            int r = idx >> 5, q = idx & 31;
            float4 v = (m0 + r < M) ? __ldg(&A4[(m0 + r) * 32 + q]) : f4zero();
            uint2 hi, lo;
            split4(v, hi, lo);
            *(uint2*)(sa_hi + r * AST + q * 4) = hi;
            *(uint2*)(sa_lo + r * AST + q * 4) = lo;
        }
    } else {
        const uint2* hh = (const uint2*)Ain;   // 4 halves per lane
#pragma unroll 1
        for (int rr = 0; rr < 8; rr++) {
            int r = wid * 8 + rr;              // 8 warps x 8 rows = 64
            int node = m0 + r;
            float4 acc = f4zero();
            if (node < M) {
                acc = h2f4(hh[node * 32 + lane]);
                int s0 = g_offs[node], s1 = g_offs[node + 1];
                int j = s0;
                for (; j + 15 < s1; j += 16) GATHER16(hh, j);
                for (; j < s1; j++) {
                    float4 u = h2f4(hh[g_perm[j] * 32 + lane]);
                    acc.x += u.x; acc.y += u.y; acc.z += u.z; acc.w += u.w;
                }
            }
            uint2 hi, lo;
            split4(acc, hi, lo);
            *(uint2*)(sa_hi + r * AST + lane * 4) = hi;
            *(uint2*)(sa_lo + r * AST + lane * 4) = lo;
        }
    }
    if (mode == 2 && tid < 64)
        sbat[tid] = (m0 + tid < M) ? g_batch[m0 + tid] : -1;
    __syncthreads();

    // ---- tensor phase: warp wid owns cols wid*16..+15, all 64 rows --------------
    wmma::fragment<wmma::accumulator, 16, 16, 16, float> facc[4];
#pragma unroll
    for (int r = 0; r < 4; r++) wmma::fill_fragment(facc[r], 0.f);

    const __nv_bfloat16* Bh = g_Wh + widx * 16384 + wid * 16;
    const __nv_bfloat16* Bl = g_Wl + widx * 16384 + wid * 16;

#pragma unroll 1
    for (int k = 0; k < 8; k++) {
        wmma::fragment<wmma::matrix_b, 16, 16, 16, __nv_bfloat16, wmma::row_major> bh, bl;
        wmma::load_matrix_sync(bh, Bh + (k * 16) * 128, 128);
        wmma::load_matrix_sync(bl, Bl + (k * 16) * 128, 128);
#pragma unroll
        for (int r = 0; r < 4; r++) {
            wmma::fragment<wmma::matrix_a, 16, 16, 16, __nv_bfloat16, wmma::row_major> ah, al;
            wmma::load_matrix_sync(ah, sa_hi + (r * 16) * AST + k * 16, AST);
            wmma::load_matrix_sync(al, sa_lo + (r * 16) * AST + k * 16, AST);
            wmma::mma_sync(facc[r], ah, bh, facc[r]);
            wmma::mma_sync(facc[r], ah, bl, facc[r]);
            wmma::mma_sync(facc[r], al, bh, facc[r]);
        }
    }

    // ---- epilogue via smem (reuse A area) ----
    __syncthreads();
    float* cs = (float*)sm;
#pragma unroll
    for (int r = 0; r < 4; r++)
        wmma::store_matrix_sync(cs + (r * 16) * CST + wid * 16,
                                facc[r], CST, wmma::mem_row_major);
    __syncthreads();

    if (mode == 2) {
        // fused mean-pool accumulate: 2 threads per column, 32 sorted rows each.
        int c = tid & 127;
        int r0 = (tid >> 7) * 32, r1 = r0 + 32;
        float b = bias ? bias[c] : 0.f;
        float acc = 0.f;
        int cur = sbat[r0];
        for (int r = r0; r < r1; r++) {
            int g = sbat[r];
            if (g < 0) break;
            if (g != cur) {
                atomicAdd(&g_pool[cur * HH + c], acc);
                acc = 0.f; cur = g;
            }
            acc += fmaxf(cs[r * CST + c] + b, 0.f);
        }
        if (cur >= 0 && acc != 0.f) atomicAdd(&g_pool[cur * HH + c], acc);
        return;
    }

    const float4* b4p = (const float4*)bias;
#pragma unroll
    for (int i = 0; i < 8; i++) {
        int idx = tid + i * 256;
        int r = idx >> 5, q = idx & 31;
        int grow = m0 + r;
        if (grow < M) {
            float4 o = *(float4*)(cs + r * CST + q * 4);
            if (bias) {
                float4 bb = b4p[q];
                o.x += bb.x; o.y += bb.y; o.z += bb.z; o.w += bb.w;
            }
            if (relu) {
                o.x = fmaxf(o.x, 0.f); o.y = fmaxf(o.y, 0.f);
                o.z = fmaxf(o.z, 0.f); o.w = fmaxf(o.w, 0.f);
            }
            if (mode == 1)
                ((uint2*)Cout)[grow * 32 + q] = f42h(o);
            else
                ((float4*)Cout)[grow * 32 + q] = o;
        }
    }
}

// ---------------- GCN aggregation (half in, half out; per-edge dinv) -------------
// out = relu(b0 + dinv_i*(dinv_i*h[i] + sum_s dinv[s]*h[s]))
__global__ void k_gcn_agg(const __half* __restrict__ h, const float* __restrict__ b0,
                          __half* __restrict__ out) {
    int node = blockIdx.x * 8 + (threadIdx.x >> 5);
    if (node >= NN) return;
    int lane = threadIdx.x & 31;
    const uint2* hh = (const uint2*)h;

    float di = g_dinv[node];
    float4 hs = h2f4(hh[node * 32 + lane]);
    float4 acc = make_float4(di * hs.x, di * hs.y, di * hs.z, di * hs.w);
    int s0 = g_offs[node], s1 = g_offs[node + 1];
    int j = s0;
    for (; j + 15 < s1; j += 16) {
        int ix[16];
#pragma unroll
        for (int t = 0; t < 16; t++) ix[t] = g_perm[j + t];
        float cc[16];
        uint2 rr[16];
#pragma unroll
        for (int t = 0; t < 16; t++) { cc[t] = g_dinv[ix[t]]; rr[t] = hh[ix[t] * 32 + lane]; }
#pragma unroll
        for (int t = 0; t < 16; t++) {
            float4 u = h2f4(rr[t]);
            acc.x = fmaf(cc[t], u.x, acc.x);
            acc.y = fmaf(cc[t], u.y, acc.y);
            acc.z = fmaf(cc[t], u.z, acc.z);
            acc.w = fmaf(cc[t], u.w, acc.w);
        }
    }
    for (; j < s1; j++) {
        int n0 = g_perm[j];
        float c0 = g_dinv[n0];
        float4 u = h2f4(hh[n0 * 32 + lane]);
        acc.x = fmaf(c0, u.x, acc.x); acc.y = fmaf(c0, u.y, acc.y);
        acc.z = fmaf(c0, u.z, acc.z); acc.w = fmaf(c0, u.w, acc.w);
    }
    float4 b = ((const float4*)b0)[lane];
    float4 o;
    o.x = fmaxf(fmaf(di, acc.x, b.x), 0.f);
    o.y = fmaxf(fmaf(di, acc.y, b.y), 0.f);
    o.z = fmaxf(fmaf(di, acc.z, b.z), 0.f);
    o.w = fmaxf(fmaf(di, acc.w, b.w), 0.f);
    ((uint2*)out)[node * 32 + lane] = f42h(o);
}

// ---------------- fused head MLP: out[g] = Wh2^T relu(Wh1^T mean_g + bh1) + bh2 --
__global__ void k_head(const float* __restrict__ Wh1, const float* __restrict__ bh1,
                       const float* __restrict__ Wh2, const float* __restrict__ bh2,
                       float* __restrict__ out) {
    __shared__ float sp[HH];       // pooled row (mean)
    __shared__ float shid[NHID];   // hidden row
    int g = blockIdx.x, c = threadIdx.x;   // 256 threads
    float inv = 1.f / fmaxf(g_cnt[g], 1.f);
    if (c < HH) sp[c] = g_pool[g * HH + c] * inv;
    __syncthreads();

    float acc = bh1[c];
#pragma unroll 8
    for (int k = 0; k < HH; k++)
        acc = fmaf(sp[k], __ldg(&Wh1[k * NHID + c]), acc);
    shid[c] = fmaxf(acc, 0.f);
    __syncthreads();

    if (c < NOUT) {
        float acc2 = bh2[c];
#pragma unroll 8
        for (int k = 0; k < NHID; k++)
            acc2 = fmaf(shid[k], __ldg(&Wh2[k * NOUT + c]), acc2);
        out[g * NOUT + c] = acc2;
    }
}

// ---------------- launch ----------------
extern "C" void kernel_launch(void* const* d_in, const int* in_sizes, int n_in,
                              void* d_out, int out_size) {
    (void)in_sizes; (void)n_in; (void)out_size;
    const float* x   = (const float*)d_in[0];
    const void*  ei  = d_in[1];
    const void*  bat = d_in[2];
    const float* W0  = (const float*)d_in[3];
    const float* b0  = (const float*)d_in[4];
    const float* Wg1 = (const float*)d_in[5];
    const float* bg1 = (const float*)d_in[6];
    const float* Wg2 = (const float*)d_in[7];
    const float* bg2 = (const float*)d_in[8];
    const float* Wh1 = (const float*)d_in[9];
    const float* bh1 = (const float*)d_in[10];
    const float* Wh2 = (const float*)d_in[11];
    const float* bh2 = (const float*)d_in[12];
    float* out = (float*)d_out;

    __half *h0, *h1, *h2;
    cudaGetSymbolAddress((void**)&h0, g_h0);
    cudaGetSymbolAddress((void**)&h1, g_h1);
    cudaGetSymbolAddress((void**)&h2, g_h2);

    // side stream + events, created once (handles persist; no device allocations)
    static cudaStream_t s2 = nullptr;
    static cudaEvent_t evA = nullptr, evB = nullptr;
    if (!s2) {
        cudaStreamCreateWithFlags(&s2, cudaStreamNonBlocking);
        cudaEventCreateWithFlags(&evA, cudaEventDisableTiming);
        cudaEventCreateWithFlags(&evB, cudaEventDisableTiming);
    }

    const int TB = 256;
    int mma_blocks = (NN + 63) / 64;     // 782
    int agg_blocks = (NN + 7) / 8;

    // setup (zero + detect + weight images)
    k_setup<<<388, TB>>>((const unsigned int*)ei, W0, Wg1, Wg2);

    // fork: GEMM1 (x @ W0 -> h0 fp16) on s2, concurrent with the CSR build chain
    cudaEventRecord(evA, 0);
    cudaStreamWaitEvent(s2, evA, 0);
    k_wmma<<<mma_blocks, 256, 0, s2>>>(x, 0, nullptr, h0, NN, 0, 0, 1);
    cudaEventRecord(evB, s2);

    // main: CSR build
    k_count<<<(EE + TB - 1) / TB, TB>>>(ei, bat);
    k_scanA<<<49, 1024>>>();
    k_scanB<<<1, 1>>>();
    k_scanC<<<49, 1024>>>();
    k_fill<<<(EE + TB - 1) / TB, TB>>>(ei);

    // join: gcn_agg needs both h0 (GEMM1) and the CSR
    cudaStreamWaitEvent(0, evB, 0);
    k_gcn_agg<<<agg_blocks, 256>>>(h0, b0, h1);
    // GIN layer 1 (fused half gather + WMMA + bias + relu -> h2 fp16)
    k_wmma<<<mma_blocks, 256>>>(h1, 1, bg1, h2, NN, 1, 1, 1);
    // GIN layer 2 (fused half gather + WMMA; epilogue pools directly, no C write)
    k_wmma<<<mma_blocks, 256>>>(h2, 2, bg2, nullptr, NN, 1, 1, 2);
    // fused head MLP
    k_head<<<GG, NHID>>>(Wh1, bh1, Wh2, bh2, out);
}